// round 7
// baseline (speedup 1.0000x reference)
#include <cuda_runtime.h>
#include <cstdint>

// Problem constants
#define BB   64
#define TT   512
#define NTOT 32768      // BB*TT
#define FF   1024
#define DD   128

// Scratch (device globals; no allocation allowed)
__device__ float g_G[DD * NTOT];       // fc1 output, layout [d][n]
__device__ float g_Y[2 * DD * NTOT];   // rows 0..127: lw0*h_fwd+lb ; 128..255: lw1*h_bwd
__device__ float g_M[BB * DD];         // sum over t of lrelu(e1)
__device__ unsigned g_whi[DD * (FF/2)];  // fc1_w hi, bf16x2 packed k-pairs, [m][k2]
__device__ unsigned g_wlo[DD * (FF/2)];  // fc1_w lo residual, bf16x2 packed

// ---------------------------------------------------------------- helpers
__device__ __forceinline__ float mtanh(float x) {
    float y;
    asm("tanh.approx.f32 %0, %1;" : "=f"(y) : "f"(x));
    return y;
}
__device__ __forceinline__ unsigned sptr(const void* p) {
    return (unsigned)__cvta_generic_to_shared(p);
}
__device__ __forceinline__ void cp16(unsigned dst, const void* src) {
    asm volatile("cp.async.cg.shared.global [%0], [%1], 16;" :: "r"(dst), "l"(src));
}
#define CP_COMMIT() asm volatile("cp.async.commit_group;")
#define CP_WAIT1()  asm volatile("cp.async.wait_group 1;")

// pack two fp32 (lo = k-even, hi = k-odd) into bf16x2 (lower 16 bits = k-even)
__device__ __forceinline__ unsigned pack_bf2(float kodd, float keven) {
    unsigned d;
    asm("cvt.rn.bf16x2.f32 %0, %1, %2;" : "=r"(d) : "f"(kodd), "f"(keven));
    return d;
}
__device__ __forceinline__ float bf_lo_val(unsigned p) {   // value of lower bf16
    return __uint_as_float(p << 16);
}
__device__ __forceinline__ float bf_hi_val(unsigned p) {   // value of upper bf16
    return __uint_as_float(p & 0xffff0000u);
}

__device__ __forceinline__ void mma_bf16(float c[4], const unsigned a[4], const unsigned b[2]) {
    asm volatile(
        "mma.sync.aligned.m16n8k16.row.col.f32.bf16.bf16.f32 "
        "{%0,%1,%2,%3}, {%4,%5,%6,%7}, {%8,%9}, {%0,%1,%2,%3};"
        : "+f"(c[0]), "+f"(c[1]), "+f"(c[2]), "+f"(c[3])
        : "r"(a[0]), "r"(a[1]), "r"(a[2]), "r"(a[3]), "r"(b[0]), "r"(b[1]));
}
__device__ __forceinline__ void mma_tf32(float c[4], const unsigned a[4], const unsigned b[2]) {
    asm volatile(
        "mma.sync.aligned.m16n8k8.row.col.f32.tf32.tf32.f32 "
        "{%0,%1,%2,%3}, {%4,%5,%6,%7}, {%8,%9}, {%0,%1,%2,%3};"
        : "+f"(c[0]), "+f"(c[1]), "+f"(c[2]), "+f"(c[3])
        : "r"(a[0]), "r"(a[1]), "r"(a[2]), "r"(a[3]), "r"(b[0]), "r"(b[1]));
}

// ----------------------------------------------------------------------------
// Kernel 0: split fc1_w into bf16 hi + residual lo, packed as k-pairs.
// ----------------------------------------------------------------------------
__global__ __launch_bounds__(256) void prep_kernel(const float* __restrict__ w)
{
    const int idx = blockIdx.x * 256 + threadIdx.x;   // 0 .. 65535
    const int m  = idx >> 9;          // 0..127
    const int k2 = idx & 511;         // 0..511
    const float w0 = w[m * FF + 2 * k2];
    const float w1 = w[m * FF + 2 * k2 + 1];
    const unsigned hi = pack_bf2(w1, w0);
    const float l0 = w0 - bf_lo_val(hi);
    const float l1 = w1 - bf_hi_val(hi);
    g_whi[idx] = hi;
    g_wlo[idx] = pack_bf2(l1, l0);
}

// ----------------------------------------------------------------------------
// Kernel 1: fc1 GEMM via bf16 3-term split (fp32-grade accuracy).
// G[d][b*TT+t] = sum_f w[d][f]*x[b][f][t] + bias[d]
// CTA tile 128(M) x 128(N), BK=32 (k2 = 16 packed pairs), 8 warps 2x4,
// warp tile 64x32. A: cp.async from pre-split g_whi/g_wlo (3-buffer ring).
// B: x split/packed in-flight (register prefetch + STS, double buffer).
// ----------------------------------------------------------------------------
#define AST2 20    // A smem row stride (uints)
#define BST2 136   // B smem row stride (uints)
#define A_U  (128 * AST2)   // 2560 uints per A array
#define B_U  (16 * BST2)    // 2176 uints per B array
// layout: Ahi[3], Alo[3], Bhi[2], Blo[2]
#define FC1_SMEM_U (6 * A_U + 4 * B_U)
#define FC1_SMEM_B (FC1_SMEM_U * 4)

__global__ __launch_bounds__(256) void fc1_bf16_kernel(const float* __restrict__ x,
                                                       const float* __restrict__ bias)
{
    extern __shared__ __align__(16) unsigned smu[];
    unsigned* Ahi[3]; unsigned* Alo[3]; unsigned* Bhi[2]; unsigned* Blo[2];
#pragma unroll
    for (int i = 0; i < 3; i++) { Ahi[i] = smu + i * A_U; Alo[i] = smu + (3 + i) * A_U; }
#pragma unroll
    for (int i = 0; i < 2; i++) { Bhi[i] = smu + 6 * A_U + i * B_U; Blo[i] = smu + 6 * A_U + (2 + i) * B_U; }

    const int tid  = threadIdx.x;
    const int lane = tid & 31;
    const int wid  = tid >> 5;
    const int g    = lane >> 2;
    const int tig  = lane & 3;
    const int wm   = (wid & 1) * 64;
    const int wn   = (wid >> 1) * 32;

    const int bt = blockIdx.y;
    const int t0 = blockIdx.x * 128;
    const float* xb = x + (size_t)bt * FF * TT;

    // A fill mapping: 2 threads per m-row, 8 uints each
    const int rowA = tid >> 1;
    const int colA = (tid & 1) * 8;
    // B fill mapping: thread handles k2-row (2 f-rows) x 8 n
    const int k2r = tid >> 4;             // 0..15
    const int n8  = (tid & 15) * 8;       // 0..120

    float c[4][4][4];
#pragma unroll
    for (int i = 0; i < 4; i++)
#pragma unroll
        for (int j = 0; j < 4; j++)
#pragma unroll
            for (int k = 0; k < 4; k++) c[i][j][k] = 0.f;

    const int NS = FF / 32;   // 32 stages

    // prologue: A stages 0,1 via cp.async; B stage 0 into regs
#pragma unroll
    for (int s = 0; s < 2; s++) {
        const unsigned* whp = g_whi + rowA * (FF/2) + s * 16 + colA;
        const unsigned* wlp = g_wlo + rowA * (FF/2) + s * 16 + colA;
        cp16(sptr(Ahi[s] + rowA * AST2 + colA), whp);
        cp16(sptr(Ahi[s] + rowA * AST2 + colA + 4), whp + 4);
        cp16(sptr(Alo[s] + rowA * AST2 + colA), wlp);
        cp16(sptr(Alo[s] + rowA * AST2 + colA + 4), wlp + 4);
        CP_COMMIT();
    }
    float4 u0, u1, v0, v1;
    {
        const float* xp = xb + (size_t)(2 * k2r) * TT + t0 + n8;
        u0 = *reinterpret_cast<const float4*>(xp);
        u1 = *reinterpret_cast<const float4*>(xp + 4);
        v0 = *reinterpret_cast<const float4*>(xp + TT);
        v1 = *reinterpret_cast<const float4*>(xp + TT + 4);
    }

    for (int s = 0; s < NS; s++) {
        // ---- split/pack B stage s into smem
        {
            unsigned* bh = Bhi[s & 1] + k2r * BST2 + n8;
            unsigned* bl = Blo[s & 1] + k2r * BST2 + n8;
            unsigned h[8], l[8];
            const float ue[8] = {u0.x, u0.y, u0.z, u0.w, u1.x, u1.y, u1.z, u1.w};
            const float vo[8] = {v0.x, v0.y, v0.z, v0.w, v1.x, v1.y, v1.z, v1.w};
#pragma unroll
            for (int i = 0; i < 8; i++) {
                h[i] = pack_bf2(vo[i], ue[i]);
                const float le = ue[i] - bf_lo_val(h[i]);
                const float lo = vo[i] - bf_hi_val(h[i]);
                l[i] = pack_bf2(lo, le);
            }
            *reinterpret_cast<uint4*>(bh)     = make_uint4(h[0], h[1], h[2], h[3]);
            *reinterpret_cast<uint4*>(bh + 4) = make_uint4(h[4], h[5], h[6], h[7]);
            *reinterpret_cast<uint4*>(bl)     = make_uint4(l[0], l[1], l[2], l[3]);
            *reinterpret_cast<uint4*>(bl + 4) = make_uint4(l[4], l[5], l[6], l[7]);
        }
        CP_WAIT1();          // A(s) landed
        __syncthreads();     // B(s) visible; buffers safe

        // ---- issue A(s+2)
        if (s + 2 < NS) {
            const int sb = (s + 2) % 3;
            const unsigned* whp = g_whi + rowA * (FF/2) + (s + 2) * 16 + colA;
            const unsigned* wlp = g_wlo + rowA * (FF/2) + (s + 2) * 16 + colA;
            cp16(sptr(Ahi[sb] + rowA * AST2 + colA), whp);
            cp16(sptr(Ahi[sb] + rowA * AST2 + colA + 4), whp + 4);
            cp16(sptr(Alo[sb] + rowA * AST2 + colA), wlp);
            cp16(sptr(Alo[sb] + rowA * AST2 + colA + 4), wlp + 4);
        }
        CP_COMMIT();

        // ---- prefetch B(s+1) into regs
        {
            const int sn = (s + 1 < NS) ? s + 1 : s;
            const float* xp = xb + (size_t)(sn * 32 + 2 * k2r) * TT + t0 + n8;
            u0 = *reinterpret_cast<const float4*>(xp);
            u1 = *reinterpret_cast<const float4*>(xp + 4);
            v0 = *reinterpret_cast<const float4*>(xp + TT);
            v1 = *reinterpret_cast<const float4*>(xp + TT + 4);
        }

        // ---- MMAs: 2 k16 steps x 3 terms x 16 tiles
        const unsigned* AH = Ahi[s % 3];
        const unsigned* AL = Alo[s % 3];
        const unsigned* BH = Bhi[s & 1];
        const unsigned* BL = Blo[s & 1];
#pragma unroll
        for (int kb = 0; kb < 16; kb += 8) {
            unsigned ah[4][4], al[4][4], bh[4][2], bl[4][2];
#pragma unroll
            for (int mt = 0; mt < 4; mt++) {
                const int m = wm + mt * 16 + g;
                ah[mt][0] = AH[m * AST2 + kb + tig];
                ah[mt][1] = AH[(m + 8) * AST2 + kb + tig];
                ah[mt][2] = AH[m * AST2 + kb + tig + 4];
                ah[mt][3] = AH[(m + 8) * AST2 + kb + tig + 4];
                al[mt][0] = AL[m * AST2 + kb + tig];
                al[mt][1] = AL[(m + 8) * AST2 + kb + tig];
                al[mt][2] = AL[m * AST2 + kb + tig + 4];
                al[mt][3] = AL[(m + 8) * AST2 + kb + tig + 4];
            }
#pragma unroll
            for (int nt = 0; nt < 4; nt++) {
                const int n = wn + nt * 8 + g;
                bh[nt][0] = BH[(kb + tig) * BST2 + n];
                bh[nt][1] = BH[(kb + tig + 4) * BST2 + n];
                bl[nt][0] = BL[(kb + tig) * BST2 + n];
                bl[nt][1] = BL[(kb + tig + 4) * BST2 + n];
            }
#pragma unroll
            for (int mt = 0; mt < 4; mt++)
#pragma unroll
                for (int nt = 0; nt < 4; nt++)
                    mma_bf16(c[mt][nt], ah[mt], bh[nt]);
#pragma unroll
            for (int mt = 0; mt < 4; mt++)
#pragma unroll
                for (int nt = 0; nt < 4; nt++)
                    mma_bf16(c[mt][nt], ah[mt], bl[nt]);
#pragma unroll
            for (int mt = 0; mt < 4; mt++)
#pragma unroll
                for (int nt = 0; nt < 4; nt++)
                    mma_bf16(c[mt][nt], al[mt], bh[nt]);
        }
    }

    // epilogue
    const int nbase = bt * TT + t0 + wn;
#pragma unroll
    for (int mt = 0; mt < 4; mt++) {
        const int dr = wm + mt * 16 + g;
        const float bv0 = bias[dr];
        const float bv1 = bias[dr + 8];
#pragma unroll
        for (int nt = 0; nt < 4; nt++) {
            const int ncol = nbase + nt * 8 + 2 * tig;
            float2 w0 = make_float2(c[mt][nt][0] + bv0, c[mt][nt][1] + bv0);
            float2 w1 = make_float2(c[mt][nt][2] + bv1, c[mt][nt][3] + bv1);
            *reinterpret_cast<float2*>(g_G + (size_t)dr * NTOT + ncol) = w0;
            *reinterpret_cast<float2*>(g_G + (size_t)(dr + 8) * NTOT + ncol) = w1;
        }
    }
}

// ----------------------------------------------------------------------------
// Kernel 2: LSTM, one direction per blockIdx.y. H=1, MUFU.TANH path.
// ----------------------------------------------------------------------------
__global__ __launch_bounds__(256) void lstm_kernel(
    const float* __restrict__ wih_f, const float* __restrict__ whh_f,
    const float* __restrict__ bih_f, const float* __restrict__ bhh_f,
    const float* __restrict__ wih_b, const float* __restrict__ whh_b,
    const float* __restrict__ bih_b, const float* __restrict__ bhh_b,
    const float* __restrict__ lout_w, const float* __restrict__ lout_b)
{
    const int n = blockIdx.x * blockDim.x + threadIdx.x;
    const int dir = blockIdx.y;

    const float* wih = dir ? wih_b : wih_f;
    const float* whh = dir ? whh_b : whh_f;
    const float* bih = dir ? bih_b : bih_f;
    const float* bhh = dir ? bhh_b : bhh_f;

    const float wi0 = 0.5f * wih[0], wh0 = 0.5f * whh[0], b0 = 0.5f * (bih[0] + bhh[0]);
    const float wi1 = 0.5f * wih[1], wh1 = 0.5f * whh[1], b1 = 0.5f * (bih[1] + bhh[1]);
    const float wi2 =        wih[2], wh2 =        whh[2], b2 =        (bih[2] + bhh[2]);
    const float wi3 = 0.5f * wih[3], wh3 = 0.5f * whh[3], b3 = 0.5f * (bih[3] + bhh[3]);

    const float lw = dir ? lout_w[1] : lout_w[0];
    const float lb = dir ? 0.f : lout_b[0];

    float h = 0.f, c = 0.f;
    if (dir == 0) {
#pragma unroll 4
        for (int d = 0; d < DD; d++) {
            const float xv = g_G[(size_t)d * NTOT + n];
            const float si = fmaf(0.5f, mtanh(fmaf(wi0, xv, fmaf(wh0, h, b0))), 0.5f);
            const float sf = fmaf(0.5f, mtanh(fmaf(wi1, xv, fmaf(wh1, h, b1))), 0.5f);
            const float tg = mtanh(fmaf(wi2, xv, fmaf(wh2, h, b2)));
            const float so = fmaf(0.5f, mtanh(fmaf(wi3, xv, fmaf(wh3, h, b3))), 0.5f);
            c = fmaf(sf, c, si * tg);
            h = so * mtanh(c);
            g_Y[(size_t)d * NTOT + n] = fmaf(lw, h, lb);
        }
    } else {
#pragma unroll 4
        for (int d = DD - 1; d >= 0; d--) {
            const float xv = g_G[(size_t)d * NTOT + n];
            const float si = fmaf(0.5f, mtanh(fmaf(wi0, xv, fmaf(wh0, h, b0))), 0.5f);
            const float sf = fmaf(0.5f, mtanh(fmaf(wi1, xv, fmaf(wh1, h, b1))), 0.5f);
            const float tg = mtanh(fmaf(wi2, xv, fmaf(wh2, h, b2)));
            const float so = fmaf(0.5f, mtanh(fmaf(wi3, xv, fmaf(wh3, h, b3))), 0.5f);
            c = fmaf(sf, c, si * tg);
            h = so * mtanh(c);
            g_Y[(size_t)(DD + d) * NTOT + n] = lw * h;
        }
    }
}

// ----------------------------------------------------------------------------
// Kernel 3a: zero the mean accumulator.
// ----------------------------------------------------------------------------
__global__ void zero_kernel()
{
    const int i = blockIdx.x * blockDim.x + threadIdx.x;
    if (i < BB * DD) g_M[i] = 0.f;
}

// ----------------------------------------------------------------------------
// Kernel 3b: e1 = (Yf+Yb)^T @ w1^T + b1 (tf32, K=128, B = Yf+Yb summed in
// the fill), lrelu, sum over t -> atomicAdd g_M.
// ----------------------------------------------------------------------------
#define ASTR 20
#define BSTR 136
#define EA_U (128 * ASTR)     // A array (fp32 floats)
#define EB_U (16 * BSTR)
#define EMB_SMEM_B ((3 * EA_U + 2 * EB_U) * 4)

__global__ __launch_bounds__(256) void emb1_mma_kernel(const float* __restrict__ w1,
                                                       const float* __restrict__ b1v)
{
    extern __shared__ __align__(16) float sme[];
    float* As[3]; float* Bs[2];
#pragma unroll
    for (int i = 0; i < 3; i++) As[i] = sme + i * EA_U;
#pragma unroll
    for (int i = 0; i < 2; i++) Bs[i] = sme + 3 * EA_U + i * EB_U;

    const int tid  = threadIdx.x;
    const int lane = tid & 31;
    const int wid  = tid >> 5;
    const int g    = lane >> 2;
    const int tig  = lane & 3;
    const int wm   = (wid & 1) * 64;
    const int wn   = (wid >> 1) * 32;

    const int n0 = blockIdx.x * 128;

    const int rowA = tid >> 1;
    const int colA = (tid & 1) * 8;
    const int kr   = tid >> 4;           // 0..15
    const int n8   = (tid & 15) * 8;

    float c[4][4][4];
#pragma unroll
    for (int i = 0; i < 4; i++)
#pragma unroll
        for (int j = 0; j < 4; j++)
#pragma unroll
            for (int k = 0; k < 4; k++) c[i][j][k] = 0.f;

    const int NS = DD / 16;   // 8 stages

#pragma unroll
    for (int s = 0; s < 2; s++) {
        const float* wp = w1 + (size_t)rowA * DD + s * 16 + colA;
        cp16(sptr(As[s] + rowA * ASTR + colA), wp);
        cp16(sptr(As[s] + rowA * ASTR + colA + 4), wp + 4);
        CP_COMMIT();
    }
    float4 f0, f1, r0, r1;
    {
        const float* yf = g_Y + (size_t)kr * NTOT + n0 + n8;
        const float* yb = yf + (size_t)DD * NTOT;
        f0 = *reinterpret_cast<const float4*>(yf);
        f1 = *reinterpret_cast<const float4*>(yf + 4);
        r0 = *reinterpret_cast<const float4*>(yb);
        r1 = *reinterpret_cast<const float4*>(yb + 4);
    }

    for (int s = 0; s < NS; s++) {
        {
            float* bp = Bs[s & 1] + kr * BSTR + n8;
            float4 s0 = make_float4(f0.x + r0.x, f0.y + r0.y, f0.z + r0.z, f0.w + r0.w);
            float4 s1 = make_float4(f1.x + r1.x, f1.y + r1.y, f1.z + r1.z, f1.w + r1.w);
            *reinterpret_cast<float4*>(bp)     = s0;
            *reinterpret_cast<float4*>(bp + 4) = s1;
        }
        CP_WAIT1();
        __syncthreads();

        if (s + 2 < NS) {
            const int sb = (s + 2) % 3;
            const float* wp = w1 + (size_t)rowA * DD + (s + 2) * 16 + colA;
            cp16(sptr(As[sb] + rowA * ASTR + colA), wp);
            cp16(sptr(As[sb] + rowA * ASTR + colA + 4), wp + 4);
        }
        CP_COMMIT();

        {
            const int sn = (s + 1 < NS) ? s + 1 : s;
            const float* yf = g_Y + (size_t)(sn * 16 + kr) * NTOT + n0 + n8;
            const float* yb = yf + (size_t)DD * NTOT;
            f0 = *reinterpret_cast<const float4*>(yf);
            f1 = *reinterpret_cast<const float4*>(yf + 4);
            r0 = *reinterpret_cast<const float4*>(yb);
            r1 = *reinterpret_cast<const float4*>(yb + 4);
        }

        const float* A = As[s % 3];
        const float* B = Bs[s & 1];
#pragma unroll
        for (int kh = 0; kh < 16; kh += 8) {
            unsigned a[4][4], b[4][2];
#pragma unroll
            for (int mt = 0; mt < 4; mt++) {
                const int m = wm + mt * 16 + g;
                a[mt][0] = __float_as_uint(A[m * ASTR + kh + tig]);
                a[mt][1] = __float_as_uint(A[(m + 8) * ASTR + kh + tig]);
                a[mt][2] = __float_as_uint(A[m * ASTR + kh + tig + 4]);
                a[mt][3] = __float_as_uint(A[(m + 8) * ASTR + kh + tig + 4]);
            }
#pragma unroll
            for (int nt = 0; nt < 4; nt++) {
                const int n = wn + nt * 8 + g;
                b[nt][0] = __float_as_uint(B[(kh + tig) * BSTR + n]);
                b[nt][1] = __float_as_uint(B[(kh + tig + 4) * BSTR + n]);
            }
#pragma unroll
            for (int mt = 0; mt < 4; mt++)
#pragma unroll
                for (int nt = 0; nt < 4; nt++)
                    mma_tf32(c[mt][nt], a[mt], b[nt]);
        }
    }

    // epilogue: bias + leaky-relu + sum over n, quad-reduce, atomicAdd
    const int bb = blockIdx.x >> 2;   // 4 n-tiles of 128 per batch
#pragma unroll
    for (int mt = 0; mt < 4; mt++) {
        const int jr = wm + mt * 16 + g;
        const float bv0 = b1v[jr];
        const float bv1 = b1v[jr + 8];
        float s0 = 0.f, s1 = 0.f;
#pragma unroll
        for (int nt = 0; nt < 4; nt++) {
            float e;
            e = c[mt][nt][0] + bv0; s0 += (e >= 0.f) ? e : 0.2f * e;
            e = c[mt][nt][1] + bv0; s0 += (e >= 0.f) ? e : 0.2f * e;
            e = c[mt][nt][2] + bv1; s1 += (e >= 0.f) ? e : 0.2f * e;
            e = c[mt][nt][3] + bv1; s1 += (e >= 0.f) ? e : 0.2f * e;
        }
        s0 += __shfl_xor_sync(0xffffffffu, s0, 1);
        s0 += __shfl_xor_sync(0xffffffffu, s0, 2);
        s1 += __shfl_xor_sync(0xffffffffu, s1, 1);
        s1 += __shfl_xor_sync(0xffffffffu, s1, 2);
        if (tig == 0) {
            atomicAdd(&g_M[bb * DD + jr], s0);
            atomicAdd(&g_M[bb * DD + jr + 8], s1);
        }
    }
}

// ----------------------------------------------------------------------------
// Kernel 4: out[b][i] = (1/T) * sum_j g_M[b][j] * emb_w2[i][j] + emb_b2[i]
// ----------------------------------------------------------------------------
__global__ __launch_bounds__(128) void out_kernel(const float* __restrict__ w2,
                                                  const float* __restrict__ b2,
                                                  float* __restrict__ out)
{
    __shared__ float m[128];
    const int b = blockIdx.x;
    const int i = threadIdx.x;
    m[i] = g_M[b * DD + i] * (1.f / (float)TT);
    __syncthreads();
    float s = b2[i];
    const float* wr = w2 + i * DD;
#pragma unroll 16
    for (int j = 0; j < DD; j++) s = fmaf(m[j], wr[j], s);
    out[b * DD + i] = s;
}

// ----------------------------------------------------------------------------
extern "C" void kernel_launch(void* const* d_in, const int* in_sizes, int n_in,
                              void* d_out, int out_size)
{
    const float* x      = (const float*)d_in[0];
    const float* fc1_w  = (const float*)d_in[1];
    const float* fc1_b  = (const float*)d_in[2];
    const float* wih_f  = (const float*)d_in[3];
    const float* whh_f  = (const float*)d_in[4];
    const float* bih_f  = (const float*)d_in[5];
    const float* bhh_f  = (const float*)d_in[6];
    const float* wih_b  = (const float*)d_in[7];
    const float* whh_b  = (const float*)d_in[8];
    const float* bih_b  = (const float*)d_in[9];
    const float* bhh_b  = (const float*)d_in[10];
    const float* lout_w = (const float*)d_in[11];
    const float* lout_b = (const float*)d_in[12];
    const float* emb_w1 = (const float*)d_in[13];
    const float* emb_b1 = (const float*)d_in[14];
    const float* emb_w2 = (const float*)d_in[15];
    const float* emb_b2 = (const float*)d_in[16];
    float* out = (float*)d_out;

    cudaFuncSetAttribute(fc1_bf16_kernel,
                         cudaFuncAttributeMaxDynamicSharedMemorySize, FC1_SMEM_B);
    cudaFuncSetAttribute(emb1_mma_kernel,
                         cudaFuncAttributeMaxDynamicSharedMemorySize, EMB_SMEM_B);

    prep_kernel<<<256, 256>>>(fc1_w);
    zero_kernel<<<(BB * DD + 255) / 256, 256>>>();
    fc1_bf16_kernel<<<dim3(TT / 128, BB), 256, FC1_SMEM_B>>>(x, fc1_b);
    lstm_kernel<<<dim3(NTOT / 256, 2), 256>>>(wih_f, whh_f, bih_f, bhh_f,
                                              wih_b, whh_b, bih_b, bhh_b,
                                              lout_w, lout_b);
    emb1_mma_kernel<<<NTOT / 128, 256, EMB_SMEM_B>>>(emb_w1, emb_b1);
    out_kernel<<<BB, 128>>>(emb_w2, emb_b2, out);
}

// round 8
// speedup vs baseline: 1.3794x; 1.3794x over previous
#include <cuda_runtime.h>
#include <cstdint>

// Problem constants
#define BB   64
#define TT   512
#define NTOT 32768      // BB*TT
#define FF   1024
#define DD   128

// Scratch (device globals; no allocation allowed)
__device__ float g_G[DD * NTOT];       // fc1 output, layout [d][n]
__device__ float g_Y[2 * DD * NTOT];   // rows 0..127: lw0*h_fwd+lb ; 128..255: lw1*h_bwd
__device__ float g_M[BB * DD];         // sum over t of lrelu(e1)

// ---------------------------------------------------------------- helpers
__device__ __forceinline__ float mtanh(float x) {
    float y;
    asm("tanh.approx.f32 %0, %1;" : "=f"(y) : "f"(x));
    return y;
}
__device__ __forceinline__ unsigned sptr(const void* p) {
    return (unsigned)__cvta_generic_to_shared(p);
}
__device__ __forceinline__ void cp16(unsigned dst, const void* src) {
    asm volatile("cp.async.cg.shared.global [%0], [%1], 16;" :: "r"(dst), "l"(src));
}
#define CP_COMMIT() asm volatile("cp.async.commit_group;")
#define CP_WAIT1()  asm volatile("cp.async.wait_group 1;")

__device__ __forceinline__ void mma_tf32(float c[4], const unsigned a[4], const unsigned b[2]) {
    asm volatile(
        "mma.sync.aligned.m16n8k8.row.col.f32.tf32.tf32.f32 "
        "{%0,%1,%2,%3}, {%4,%5,%6,%7}, {%8,%9}, {%0,%1,%2,%3};"
        : "+f"(c[0]), "+f"(c[1]), "+f"(c[2]), "+f"(c[3])
        : "r"(a[0]), "r"(a[1]), "r"(a[2]), "r"(a[3]), "r"(b[0]), "r"(b[1]));
}

// ============================================================================
// Kernel 1: fc1 GEMM (tf32). CTA 128(M) x 256(N), 8 warps 2x4, warp 64x64,
// BK=16, 3-stage cp.async ring.  G[d][b*TT+t] = sum_f w[d][f]*x[b][f][t]+bias
// ============================================================================
#define ASTR 20
#define BSTR 264
#define A_FL (128 * ASTR)
#define B_FL (16 * BSTR)
#define STG_FL (A_FL + B_FL)
#define GSMEM_BYTES (3 * STG_FL * 4)

__global__ __launch_bounds__(256, 1) void fc1_mma_kernel(const float* __restrict__ x,
                                                         const float* __restrict__ w,
                                                         const float* __restrict__ bias)
{
    extern __shared__ __align__(16) float sm[];

    const int tid  = threadIdx.x;
    const int lane = tid & 31;
    const int wid  = tid >> 5;
    const int g    = lane >> 2;
    const int tig  = lane & 3;
    const int wm   = (wid & 1) * 64;
    const int wn   = (wid >> 1) * 64;

    const int bt = blockIdx.y;
    const int t0 = blockIdx.x * 256;
    const float* xb = x + (size_t)bt * FF * TT;

    const int rowA = tid >> 1;
    const int kA   = (tid & 1) * 8;
    const int rowB = tid >> 4;
    const int nB   = (tid & 15) * 16;

    unsigned aAddr[3], bAddr[3];
#pragma unroll
    for (int st = 0; st < 3; st++) {
        aAddr[st] = sptr(sm + st * STG_FL + rowA * ASTR + kA);
        bAddr[st] = sptr(sm + st * STG_FL + A_FL + rowB * BSTR + nB);
    }

    float c[4][8][4];
#pragma unroll
    for (int i = 0; i < 4; i++)
#pragma unroll
        for (int j = 0; j < 8; j++)
#pragma unroll
            for (int k = 0; k < 4; k++) c[i][j][k] = 0.f;

#pragma unroll
    for (int s = 0; s < 2; s++) {
        const float* wp = w + (size_t)rowA * FF + s * 16 + kA;
        cp16(aAddr[s], wp); cp16(aAddr[s] + 16, wp + 4);
        const float* xp = xb + (size_t)(s * 16 + rowB) * TT + t0 + nB;
        cp16(bAddr[s], xp); cp16(bAddr[s] + 16, xp + 4);
        cp16(bAddr[s] + 32, xp + 8); cp16(bAddr[s] + 48, xp + 12);
        CP_COMMIT();
    }

    const int NS = FF / 16;   // 64 stages
    for (int s = 0; s < NS; s++) {
        CP_WAIT1();
        __syncthreads();

        if (s + 2 < NS) {
            const int f0 = (s + 2) * 16;
            const int b2 = (s + 2) % 3;
            const float* wp = w + (size_t)rowA * FF + f0 + kA;
            cp16(aAddr[b2], wp); cp16(aAddr[b2] + 16, wp + 4);
            const float* xp = xb + (size_t)(f0 + rowB) * TT + t0 + nB;
            cp16(bAddr[b2], xp); cp16(bAddr[b2] + 16, xp + 4);
            cp16(bAddr[b2] + 32, xp + 8); cp16(bAddr[b2] + 48, xp + 12);
        }
        CP_COMMIT();

        const float* A = sm + (s % 3) * STG_FL;
        const float* B = A + A_FL;
#pragma unroll
        for (int kh = 0; kh < 16; kh += 8) {
            unsigned a[4][4], b[8][2];
#pragma unroll
            for (int mt = 0; mt < 4; mt++) {
                const int m = wm + mt * 16 + g;
                a[mt][0] = __float_as_uint(A[m * ASTR + kh + tig]);
                a[mt][1] = __float_as_uint(A[(m + 8) * ASTR + kh + tig]);
                a[mt][2] = __float_as_uint(A[m * ASTR + kh + tig + 4]);
                a[mt][3] = __float_as_uint(A[(m + 8) * ASTR + kh + tig + 4]);
            }
#pragma unroll
            for (int nt = 0; nt < 8; nt++) {
                const int n = wn + nt * 8 + g;
                b[nt][0] = __float_as_uint(B[(kh + tig) * BSTR + n]);
                b[nt][1] = __float_as_uint(B[(kh + tig + 4) * BSTR + n]);
            }
#pragma unroll
            for (int mt = 0; mt < 4; mt++)
#pragma unroll
                for (int nt = 0; nt < 8; nt++)
                    mma_tf32(c[mt][nt], a[mt], b[nt]);
        }
    }

    const int nbase = bt * TT + t0 + wn;
#pragma unroll
    for (int mt = 0; mt < 4; mt++) {
        const int dr = wm + mt * 16 + g;
        const float bv0 = bias[dr];
        const float bv1 = bias[dr + 8];
#pragma unroll
        for (int nt = 0; nt < 8; nt++) {
            const int ncol = nbase + nt * 8 + 2 * tig;
            float2 v0 = make_float2(c[mt][nt][0] + bv0, c[mt][nt][1] + bv0);
            float2 v1 = make_float2(c[mt][nt][2] + bv1, c[mt][nt][3] + bv1);
            *reinterpret_cast<float2*>(g_G + (size_t)dr * NTOT + ncol) = v0;
            *reinterpret_cast<float2*>(g_G + (size_t)(dr + 8) * NTOT + ncol) = v1;
        }
    }
}

// ============================================================================
// Kernel 2: LSTM, 2 sequences per thread (float2), one direction per
// blockIdx.y. Two interleaved recurrences double per-warp ILP on the
// MUFU.TANH critical path.
// ============================================================================
__global__ __launch_bounds__(128) void lstm_kernel(
    const float* __restrict__ wih_f, const float* __restrict__ whh_f,
    const float* __restrict__ bih_f, const float* __restrict__ bhh_f,
    const float* __restrict__ wih_b, const float* __restrict__ whh_b,
    const float* __restrict__ bih_b, const float* __restrict__ bhh_b,
    const float* __restrict__ lout_w, const float* __restrict__ lout_b)
{
    const int n   = (blockIdx.x * 128 + threadIdx.x) * 2;
    const int dir = blockIdx.y;

    const float* wih = dir ? wih_b : wih_f;
    const float* whh = dir ? whh_b : whh_f;
    const float* bih = dir ? bih_b : bih_f;
    const float* bhh = dir ? bhh_b : bhh_f;

    const float wi0 = 0.5f * wih[0], wh0 = 0.5f * whh[0], b0 = 0.5f * (bih[0] + bhh[0]);
    const float wi1 = 0.5f * wih[1], wh1 = 0.5f * whh[1], b1 = 0.5f * (bih[1] + bhh[1]);
    const float wi2 =        wih[2], wh2 =        whh[2], b2 =        (bih[2] + bhh[2]);
    const float wi3 = 0.5f * wih[3], wh3 = 0.5f * whh[3], b3 = 0.5f * (bih[3] + bhh[3]);

    const float lw = dir ? lout_w[1] : lout_w[0];
    const float lb = dir ? 0.f : lout_b[0];

    float hx = 0.f, cx = 0.f, hy = 0.f, cy = 0.f;

    const int d0   = dir ? DD - 1 : 0;
    const int dstp = dir ? -1 : 1;
    const size_t ybase = dir ? (size_t)DD * NTOT : 0;

#pragma unroll 2
    for (int it = 0; it < DD; it++) {
        const int d = d0 + dstp * it;
        const float2 xv = *reinterpret_cast<const float2*>(g_G + (size_t)d * NTOT + n);

        const float aix = fmaf(wi0, xv.x, fmaf(wh0, hx, b0));
        const float aiy = fmaf(wi0, xv.y, fmaf(wh0, hy, b0));
        const float afx = fmaf(wi1, xv.x, fmaf(wh1, hx, b1));
        const float afy = fmaf(wi1, xv.y, fmaf(wh1, hy, b1));
        const float agx = fmaf(wi2, xv.x, fmaf(wh2, hx, b2));
        const float agy = fmaf(wi2, xv.y, fmaf(wh2, hy, b2));
        const float aox = fmaf(wi3, xv.x, fmaf(wh3, hx, b3));
        const float aoy = fmaf(wi3, xv.y, fmaf(wh3, hy, b3));

        const float six = fmaf(0.5f, mtanh(aix), 0.5f);
        const float siy = fmaf(0.5f, mtanh(aiy), 0.5f);
        const float sfx = fmaf(0.5f, mtanh(afx), 0.5f);
        const float sfy = fmaf(0.5f, mtanh(afy), 0.5f);
        const float tgx = mtanh(agx);
        const float tgy = mtanh(agy);
        const float sox = fmaf(0.5f, mtanh(aox), 0.5f);
        const float soy = fmaf(0.5f, mtanh(aoy), 0.5f);

        cx = fmaf(sfx, cx, six * tgx);
        cy = fmaf(sfy, cy, siy * tgy);
        hx = sox * mtanh(cx);
        hy = soy * mtanh(cy);

        float2 yv = make_float2(fmaf(lw, hx, lb), fmaf(lw, hy, lb));
        *reinterpret_cast<float2*>(g_Y + ybase + (size_t)d * NTOT + n) = yv;
    }
}

// ============================================================================
// Kernel 3a: zero the mean accumulator.
// ============================================================================
__global__ void zero_kernel()
{
    const int i = blockIdx.x * blockDim.x + threadIdx.x;
    if (i < BB * DD) g_M[i] = 0.f;
}

// ============================================================================
// Kernel 3b: e1 = (Yf+Yb)^T @ w1^T + b1 (tf32, K=128, Yf+Yb summed during
// the B fill), lrelu, sum over t -> atomicAdd g_M.
// ============================================================================
#define EBSTR 136
#define EA_U (128 * ASTR)
#define EB_U (16 * EBSTR)
#define EMB_SMEM_B ((3 * EA_U + 2 * EB_U) * 4)

__global__ __launch_bounds__(256) void emb1_mma_kernel(const float* __restrict__ w1,
                                                       const float* __restrict__ b1v)
{
    extern __shared__ __align__(16) float sme[];
    float* As[3]; float* Bs[2];
#pragma unroll
    for (int i = 0; i < 3; i++) As[i] = sme + i * EA_U;
#pragma unroll
    for (int i = 0; i < 2; i++) Bs[i] = sme + 3 * EA_U + i * EB_U;

    const int tid  = threadIdx.x;
    const int lane = tid & 31;
    const int wid  = tid >> 5;
    const int g    = lane >> 2;
    const int tig  = lane & 3;
    const int wm   = (wid & 1) * 64;
    const int wn   = (wid >> 1) * 32;

    const int n0 = blockIdx.x * 128;

    const int rowA = tid >> 1;
    const int colA = (tid & 1) * 8;
    const int kr   = tid >> 4;
    const int n8   = (tid & 15) * 8;

    float c[4][4][4];
#pragma unroll
    for (int i = 0; i < 4; i++)
#pragma unroll
        for (int j = 0; j < 4; j++)
#pragma unroll
            for (int k = 0; k < 4; k++) c[i][j][k] = 0.f;

    const int NS = DD / 16;   // 8 stages

#pragma unroll
    for (int s = 0; s < 2; s++) {
        const float* wp = w1 + (size_t)rowA * DD + s * 16 + colA;
        cp16(sptr(As[s] + rowA * ASTR + colA), wp);
        cp16(sptr(As[s] + rowA * ASTR + colA + 4), wp + 4);
        CP_COMMIT();
    }
    float4 f0, f1, r0, r1;
    {
        const float* yf = g_Y + (size_t)kr * NTOT + n0 + n8;
        const float* yb = yf + (size_t)DD * NTOT;
        f0 = *reinterpret_cast<const float4*>(yf);
        f1 = *reinterpret_cast<const float4*>(yf + 4);
        r0 = *reinterpret_cast<const float4*>(yb);
        r1 = *reinterpret_cast<const float4*>(yb + 4);
    }

    for (int s = 0; s < NS; s++) {
        {
            float* bp = Bs[s & 1] + kr * EBSTR + n8;
            float4 s0 = make_float4(f0.x + r0.x, f0.y + r0.y, f0.z + r0.z, f0.w + r0.w);
            float4 s1 = make_float4(f1.x + r1.x, f1.y + r1.y, f1.z + r1.z, f1.w + r1.w);
            *reinterpret_cast<float4*>(bp)     = s0;
            *reinterpret_cast<float4*>(bp + 4) = s1;
        }
        CP_WAIT1();
        __syncthreads();

        if (s + 2 < NS) {
            const int sb = (s + 2) % 3;
            const float* wp = w1 + (size_t)rowA * DD + (s + 2) * 16 + colA;
            cp16(sptr(As[sb] + rowA * ASTR + colA), wp);
            cp16(sptr(As[sb] + rowA * ASTR + colA + 4), wp + 4);
        }
        CP_COMMIT();

        {
            const int sn = (s + 1 < NS) ? s + 1 : s;
            const float* yf = g_Y + (size_t)(sn * 16 + kr) * NTOT + n0 + n8;
            const float* yb = yf + (size_t)DD * NTOT;
            f0 = *reinterpret_cast<const float4*>(yf);
            f1 = *reinterpret_cast<const float4*>(yf + 4);
            r0 = *reinterpret_cast<const float4*>(yb);
            r1 = *reinterpret_cast<const float4*>(yb + 4);
        }

        const float* A = As[s % 3];
        const float* B = Bs[s & 1];
#pragma unroll
        for (int kh = 0; kh < 16; kh += 8) {
            unsigned a[4][4], b[4][2];
#pragma unroll
            for (int mt = 0; mt < 4; mt++) {
                const int m = wm + mt * 16 + g;
                a[mt][0] = __float_as_uint(A[m * ASTR + kh + tig]);
                a[mt][1] = __float_as_uint(A[(m + 8) * ASTR + kh + tig]);
                a[mt][2] = __float_as_uint(A[m * ASTR + kh + tig + 4]);
                a[mt][3] = __float_as_uint(A[(m + 8) * ASTR + kh + tig + 4]);
            }
#pragma unroll
            for (int nt = 0; nt < 4; nt++) {
                const int n = wn + nt * 8 + g;
                b[nt][0] = __float_as_uint(B[(kh + tig) * EBSTR + n]);
                b[nt][1] = __float_as_uint(B[(kh + tig + 4) * EBSTR + n]);
            }
#pragma unroll
            for (int mt = 0; mt < 4; mt++)
#pragma unroll
                for (int nt = 0; nt < 4; nt++)
                    mma_tf32(c[mt][nt], a[mt], b[nt]);
        }
    }

    const int bb = blockIdx.x >> 2;
#pragma unroll
    for (int mt = 0; mt < 4; mt++) {
        const int jr = wm + mt * 16 + g;
        const float bv0 = b1v[jr];
        const float bv1 = b1v[jr + 8];
        float s0 = 0.f, s1 = 0.f;
#pragma unroll
        for (int nt = 0; nt < 4; nt++) {
            float e;
            e = c[mt][nt][0] + bv0; s0 += (e >= 0.f) ? e : 0.2f * e;
            e = c[mt][nt][1] + bv0; s0 += (e >= 0.f) ? e : 0.2f * e;
            e = c[mt][nt][2] + bv1; s1 += (e >= 0.f) ? e : 0.2f * e;
            e = c[mt][nt][3] + bv1; s1 += (e >= 0.f) ? e : 0.2f * e;
        }
        s0 += __shfl_xor_sync(0xffffffffu, s0, 1);
        s0 += __shfl_xor_sync(0xffffffffu, s0, 2);
        s1 += __shfl_xor_sync(0xffffffffu, s1, 1);
        s1 += __shfl_xor_sync(0xffffffffu, s1, 2);
        if (tig == 0) {
            atomicAdd(&g_M[bb * DD + jr], s0);
            atomicAdd(&g_M[bb * DD + jr + 8], s1);
        }
    }
}

// ============================================================================
// Kernel 4: out[b][i] = (1/T) * sum_j g_M[b][j] * emb_w2[i][j] + emb_b2[i]
// ============================================================================
__global__ __launch_bounds__(128) void out_kernel(const float* __restrict__ w2,
                                                  const float* __restrict__ b2,
                                                  float* __restrict__ out)
{
    __shared__ float m[128];
    const int b = blockIdx.x;
    const int i = threadIdx.x;
    m[i] = g_M[b * DD + i] * (1.f / (float)TT);
    __syncthreads();
    float s = b2[i];
    const float* wr = w2 + i * DD;
#pragma unroll 16
    for (int j = 0; j < DD; j++) s = fmaf(m[j], wr[j], s);
    out[b * DD + i] = s;
}

// ----------------------------------------------------------------------------
extern "C" void kernel_launch(void* const* d_in, const int* in_sizes, int n_in,
                              void* d_out, int out_size)
{
    const float* x      = (const float*)d_in[0];
    const float* fc1_w  = (const float*)d_in[1];
    const float* fc1_b  = (const float*)d_in[2];
    const float* wih_f  = (const float*)d_in[3];
    const float* whh_f  = (const float*)d_in[4];
    const float* bih_f  = (const float*)d_in[5];
    const float* bhh_f  = (const float*)d_in[6];
    const float* wih_b  = (const float*)d_in[7];
    const float* whh_b  = (const float*)d_in[8];
    const float* bih_b  = (const float*)d_in[9];
    const float* bhh_b  = (const float*)d_in[10];
    const float* lout_w = (const float*)d_in[11];
    const float* lout_b = (const float*)d_in[12];
    const float* emb_w1 = (const float*)d_in[13];
    const float* emb_b1 = (const float*)d_in[14];
    const float* emb_w2 = (const float*)d_in[15];
    const float* emb_b2 = (const float*)d_in[16];
    float* out = (float*)d_out;

    cudaFuncSetAttribute(fc1_mma_kernel,
                         cudaFuncAttributeMaxDynamicSharedMemorySize, GSMEM_BYTES);
    cudaFuncSetAttribute(emb1_mma_kernel,
                         cudaFuncAttributeMaxDynamicSharedMemorySize, EMB_SMEM_B);

    fc1_mma_kernel<<<dim3(TT / 256, BB), 256, GSMEM_BYTES>>>(x, fc1_w, fc1_b);
    zero_kernel<<<(BB * DD + 255) / 256, 256>>>();
    lstm_kernel<<<dim3(NTOT / 256, 2), 128>>>(wih_f, whh_f, bih_f, bhh_f,
                                              wih_b, whh_b, bih_b, bhh_b,
                                              lout_w, lout_b);
    emb1_mma_kernel<<<NTOT / 128, 256, EMB_SMEM_B>>>(emb_w1, emb_b1);
    out_kernel<<<BB, 128>>>(emb_w2, emb_b2, out);
}

// round 9
// speedup vs baseline: 1.6254x; 1.1783x over previous
#include <cuda_runtime.h>
#include <cstdint>

// Problem constants
#define BB   64
#define TT   512
#define NTOT 32768      // BB*TT
#define FF   1024
#define DD   128

// Scratch (device globals; no allocation allowed)
__device__ float g_G[DD * NTOT];       // fc1 output, layout [d][n]
__device__ float g_Y[2 * DD * NTOT];   // rows 0..127: lw0*h_fwd+lb ; 128..255: lw1*h_bwd
__device__ float g_M[BB * DD];         // sum over t of lrelu(e1)

// ---------------------------------------------------------------- helpers
__device__ __forceinline__ float mtanh(float x) {
    float y;
    asm("tanh.approx.f32 %0, %1;" : "=f"(y) : "f"(x));
    return y;
}
__device__ __forceinline__ unsigned sptr(const void* p) {
    return (unsigned)__cvta_generic_to_shared(p);
}
__device__ __forceinline__ void cp16(unsigned dst, const void* src) {
    asm volatile("cp.async.cg.shared.global [%0], [%1], 16;" :: "r"(dst), "l"(src));
}
#define CP_COMMIT() asm volatile("cp.async.commit_group;")
#define CP_WAIT1()  asm volatile("cp.async.wait_group 1;")

__device__ __forceinline__ void mma_tf32(float c[4], const unsigned a[4], const unsigned b[2]) {
    asm volatile(
        "mma.sync.aligned.m16n8k8.row.col.f32.tf32.tf32.f32 "
        "{%0,%1,%2,%3}, {%4,%5,%6,%7}, {%8,%9}, {%0,%1,%2,%3};"
        : "+f"(c[0]), "+f"(c[1]), "+f"(c[2]), "+f"(c[3])
        : "r"(a[0]), "r"(a[1]), "r"(a[2]), "r"(a[3]), "r"(b[0]), "r"(b[1]));
}

// ============================================================================
// Kernel 1: fc1 GEMM (tf32). CTA 128(M) x 256(N), 8 warps 2x4, warp 64x64,
// BK=16, 3-stage cp.async ring.  G[d][b*TT+t] = sum_f w[d][f]*x[b][f][t]+bias
// ============================================================================
#define ASTR 20
#define BSTR 264
#define A_FL (128 * ASTR)
#define B_FL (16 * BSTR)
#define STG_FL (A_FL + B_FL)
#define GSMEM_BYTES (3 * STG_FL * 4)

__global__ __launch_bounds__(256, 1) void fc1_mma_kernel(const float* __restrict__ x,
                                                         const float* __restrict__ w,
                                                         const float* __restrict__ bias)
{
    extern __shared__ __align__(16) float sm[];

    const int tid  = threadIdx.x;
    const int lane = tid & 31;
    const int wid  = tid >> 5;
    const int g    = lane >> 2;
    const int tig  = lane & 3;
    const int wm   = (wid & 1) * 64;
    const int wn   = (wid >> 1) * 64;

    const int bt = blockIdx.y;
    const int t0 = blockIdx.x * 256;
    const float* xb = x + (size_t)bt * FF * TT;

    const int rowA = tid >> 1;
    const int kA   = (tid & 1) * 8;
    const int rowB = tid >> 4;
    const int nB   = (tid & 15) * 16;

    unsigned aAddr[3], bAddr[3];
#pragma unroll
    for (int st = 0; st < 3; st++) {
        aAddr[st] = sptr(sm + st * STG_FL + rowA * ASTR + kA);
        bAddr[st] = sptr(sm + st * STG_FL + A_FL + rowB * BSTR + nB);
    }

    float c[4][8][4];
#pragma unroll
    for (int i = 0; i < 4; i++)
#pragma unroll
        for (int j = 0; j < 8; j++)
#pragma unroll
            for (int k = 0; k < 4; k++) c[i][j][k] = 0.f;

#pragma unroll
    for (int s = 0; s < 2; s++) {
        const float* wp = w + (size_t)rowA * FF + s * 16 + kA;
        cp16(aAddr[s], wp); cp16(aAddr[s] + 16, wp + 4);
        const float* xp = xb + (size_t)(s * 16 + rowB) * TT + t0 + nB;
        cp16(bAddr[s], xp); cp16(bAddr[s] + 16, xp + 4);
        cp16(bAddr[s] + 32, xp + 8); cp16(bAddr[s] + 48, xp + 12);
        CP_COMMIT();
    }

    const int NS = FF / 16;   // 64 stages
    for (int s = 0; s < NS; s++) {
        CP_WAIT1();
        __syncthreads();

        if (s + 2 < NS) {
            const int f0 = (s + 2) * 16;
            const int b2 = (s + 2) % 3;
            const float* wp = w + (size_t)rowA * FF + f0 + kA;
            cp16(aAddr[b2], wp); cp16(aAddr[b2] + 16, wp + 4);
            const float* xp = xb + (size_t)(f0 + rowB) * TT + t0 + nB;
            cp16(bAddr[b2], xp); cp16(bAddr[b2] + 16, xp + 4);
            cp16(bAddr[b2] + 32, xp + 8); cp16(bAddr[b2] + 48, xp + 12);
        }
        CP_COMMIT();

        const float* A = sm + (s % 3) * STG_FL;
        const float* B = A + A_FL;
#pragma unroll
        for (int kh = 0; kh < 16; kh += 8) {
            unsigned a[4][4], b[8][2];
#pragma unroll
            for (int mt = 0; mt < 4; mt++) {
                const int m = wm + mt * 16 + g;
                a[mt][0] = __float_as_uint(A[m * ASTR + kh + tig]);
                a[mt][1] = __float_as_uint(A[(m + 8) * ASTR + kh + tig]);
                a[mt][2] = __float_as_uint(A[m * ASTR + kh + tig + 4]);
                a[mt][3] = __float_as_uint(A[(m + 8) * ASTR + kh + tig + 4]);
            }
#pragma unroll
            for (int nt = 0; nt < 8; nt++) {
                const int n = wn + nt * 8 + g;
                b[nt][0] = __float_as_uint(B[(kh + tig) * BSTR + n]);
                b[nt][1] = __float_as_uint(B[(kh + tig + 4) * BSTR + n]);
            }
#pragma unroll
            for (int mt = 0; mt < 4; mt++)
#pragma unroll
                for (int nt = 0; nt < 8; nt++)
                    mma_tf32(c[mt][nt], a[mt], b[nt]);
        }
    }

    const int nbase = bt * TT + t0 + wn;
#pragma unroll
    for (int mt = 0; mt < 4; mt++) {
        const int dr = wm + mt * 16 + g;
        const float bv0 = bias[dr];
        const float bv1 = bias[dr + 8];
#pragma unroll
        for (int nt = 0; nt < 8; nt++) {
            const int ncol = nbase + nt * 8 + 2 * tig;
            float2 v0 = make_float2(c[mt][nt][0] + bv0, c[mt][nt][1] + bv0);
            float2 v1 = make_float2(c[mt][nt][2] + bv1, c[mt][nt][3] + bv1);
            *reinterpret_cast<float2*>(g_G + (size_t)dr * NTOT + ncol) = v0;
            *reinterpret_cast<float2*>(g_G + (size_t)(dr + 8) * NTOT + ncol) = v1;
        }
    }
}

// ============================================================================
// Kernel 2: LSTM, 2 sequences per thread (float2), one direction per
// blockIdx.y, with an 8-deep register prefetch ring on the g_G loads so the
// recurrence never waits on DRAM latency.
// ============================================================================
#define PF 8

__global__ __launch_bounds__(128) void lstm_kernel(
    const float* __restrict__ wih_f, const float* __restrict__ whh_f,
    const float* __restrict__ bih_f, const float* __restrict__ bhh_f,
    const float* __restrict__ wih_b, const float* __restrict__ whh_b,
    const float* __restrict__ bih_b, const float* __restrict__ bhh_b,
    const float* __restrict__ lout_w, const float* __restrict__ lout_b)
{
    const int n   = (blockIdx.x * 128 + threadIdx.x) * 2;
    const int dir = blockIdx.y;

    const float* wih = dir ? wih_b : wih_f;
    const float* whh = dir ? whh_b : whh_f;
    const float* bih = dir ? bih_b : bih_f;
    const float* bhh = dir ? bhh_b : bhh_f;

    const float wi0 = 0.5f * wih[0], wh0 = 0.5f * whh[0], b0 = 0.5f * (bih[0] + bhh[0]);
    const float wi1 = 0.5f * wih[1], wh1 = 0.5f * whh[1], b1 = 0.5f * (bih[1] + bhh[1]);
    const float wi2 =        wih[2], wh2 =        whh[2], b2 =        (bih[2] + bhh[2]);
    const float wi3 = 0.5f * wih[3], wh3 = 0.5f * whh[3], b3 = 0.5f * (bih[3] + bhh[3]);

    const float lw = dir ? lout_w[1] : lout_w[0];
    const float lb = dir ? 0.f : lout_b[0];

    const int d0   = dir ? DD - 1 : 0;
    const int dstp = dir ? -1 : 1;
    const size_t ybase = dir ? (size_t)DD * NTOT : 0;

    float hx = 0.f, cx = 0.f, hy = 0.f, cy = 0.f;

    // prefetch ring
    float2 q[PF];
#pragma unroll
    for (int p = 0; p < PF; p++)
        q[p] = *reinterpret_cast<const float2*>(g_G + (size_t)(d0 + dstp * p) * NTOT + n);

#pragma unroll 8
    for (int it = 0; it < DD; it++) {
        const int d = d0 + dstp * it;
        const float2 xv = q[it % PF];
        if (it + PF < DD)
            q[it % PF] = *reinterpret_cast<const float2*>(
                g_G + (size_t)(d0 + dstp * (it + PF)) * NTOT + n);

        const float aix = fmaf(wi0, xv.x, fmaf(wh0, hx, b0));
        const float aiy = fmaf(wi0, xv.y, fmaf(wh0, hy, b0));
        const float afx = fmaf(wi1, xv.x, fmaf(wh1, hx, b1));
        const float afy = fmaf(wi1, xv.y, fmaf(wh1, hy, b1));
        const float agx = fmaf(wi2, xv.x, fmaf(wh2, hx, b2));
        const float agy = fmaf(wi2, xv.y, fmaf(wh2, hy, b2));
        const float aox = fmaf(wi3, xv.x, fmaf(wh3, hx, b3));
        const float aoy = fmaf(wi3, xv.y, fmaf(wh3, hy, b3));

        const float six = fmaf(0.5f, mtanh(aix), 0.5f);
        const float siy = fmaf(0.5f, mtanh(aiy), 0.5f);
        const float sfx = fmaf(0.5f, mtanh(afx), 0.5f);
        const float sfy = fmaf(0.5f, mtanh(afy), 0.5f);
        const float tgx = mtanh(agx);
        const float tgy = mtanh(agy);
        const float sox = fmaf(0.5f, mtanh(aox), 0.5f);
        const float soy = fmaf(0.5f, mtanh(aoy), 0.5f);

        cx = fmaf(sfx, cx, six * tgx);
        cy = fmaf(sfy, cy, siy * tgy);
        hx = sox * mtanh(cx);
        hy = soy * mtanh(cy);

        float2 yv = make_float2(fmaf(lw, hx, lb), fmaf(lw, hy, lb));
        *reinterpret_cast<float2*>(g_Y + ybase + (size_t)d * NTOT + n) = yv;
    }
}

// ============================================================================
// Kernel 3a: zero the mean accumulator.
// ============================================================================
__global__ void zero_kernel()
{
    const int i = blockIdx.x * blockDim.x + threadIdx.x;
    if (i < BB * DD) g_M[i] = 0.f;
}

// ============================================================================
// Kernel 3b: e1 = (Yf+Yb)^T @ w1^T + b1 (tf32, K=128, Yf+Yb summed during
// the B fill), lrelu, sum over t -> atomicAdd g_M.
// ============================================================================
#define EBSTR 136
#define EA_U (128 * ASTR)
#define EB_U (16 * EBSTR)
#define EMB_SMEM_B ((3 * EA_U + 2 * EB_U) * 4)

__global__ __launch_bounds__(256) void emb1_mma_kernel(const float* __restrict__ w1,
                                                       const float* __restrict__ b1v)
{
    extern __shared__ __align__(16) float sme[];
    float* As[3]; float* Bs[2];
#pragma unroll
    for (int i = 0; i < 3; i++) As[i] = sme + i * EA_U;
#pragma unroll
    for (int i = 0; i < 2; i++) Bs[i] = sme + 3 * EA_U + i * EB_U;

    const int tid  = threadIdx.x;
    const int lane = tid & 31;
    const int wid  = tid >> 5;
    const int g    = lane >> 2;
    const int tig  = lane & 3;
    const int wm   = (wid & 1) * 64;
    const int wn   = (wid >> 1) * 32;

    const int n0 = blockIdx.x * 128;

    const int rowA = tid >> 1;
    const int colA = (tid & 1) * 8;
    const int kr   = tid >> 4;
    const int n8   = (tid & 15) * 8;

    float c[4][4][4];
#pragma unroll
    for (int i = 0; i < 4; i++)
#pragma unroll
        for (int j = 0; j < 4; j++)
#pragma unroll
            for (int k = 0; k < 4; k++) c[i][j][k] = 0.f;

    const int NS = DD / 16;   // 8 stages

#pragma unroll
    for (int s = 0; s < 2; s++) {
        const float* wp = w1 + (size_t)rowA * DD + s * 16 + colA;
        cp16(sptr(As[s] + rowA * ASTR + colA), wp);
        cp16(sptr(As[s] + rowA * ASTR + colA + 4), wp + 4);
        CP_COMMIT();
    }
    float4 f0, f1, r0, r1;
    {
        const float* yf = g_Y + (size_t)kr * NTOT + n0 + n8;
        const float* yb = yf + (size_t)DD * NTOT;
        f0 = *reinterpret_cast<const float4*>(yf);
        f1 = *reinterpret_cast<const float4*>(yf + 4);
        r0 = *reinterpret_cast<const float4*>(yb);
        r1 = *reinterpret_cast<const float4*>(yb + 4);
    }

    for (int s = 0; s < NS; s++) {
        {
            float* bp = Bs[s & 1] + kr * EBSTR + n8;
            float4 s0 = make_float4(f0.x + r0.x, f0.y + r0.y, f0.z + r0.z, f0.w + r0.w);
            float4 s1 = make_float4(f1.x + r1.x, f1.y + r1.y, f1.z + r1.z, f1.w + r1.w);
            *reinterpret_cast<float4*>(bp)     = s0;
            *reinterpret_cast<float4*>(bp + 4) = s1;
        }
        CP_WAIT1();
        __syncthreads();

        if (s + 2 < NS) {
            const int sb = (s + 2) % 3;
            const float* wp = w1 + (size_t)rowA * DD + (s + 2) * 16 + colA;
            cp16(sptr(As[sb] + rowA * ASTR + colA), wp);
            cp16(sptr(As[sb] + rowA * ASTR + colA + 4), wp + 4);
        }
        CP_COMMIT();

        {
            const int sn = (s + 1 < NS) ? s + 1 : s;
            const float* yf = g_Y + (size_t)(sn * 16 + kr) * NTOT + n0 + n8;
            const float* yb = yf + (size_t)DD * NTOT;
            f0 = *reinterpret_cast<const float4*>(yf);
            f1 = *reinterpret_cast<const float4*>(yf + 4);
            r0 = *reinterpret_cast<const float4*>(yb);
            r1 = *reinterpret_cast<const float4*>(yb + 4);
        }

        const float* A = As[s % 3];
        const float* B = Bs[s & 1];
#pragma unroll
        for (int kh = 0; kh < 16; kh += 8) {
            unsigned a[4][4], b[4][2];
#pragma unroll
            for (int mt = 0; mt < 4; mt++) {
                const int m = wm + mt * 16 + g;
                a[mt][0] = __float_as_uint(A[m * ASTR + kh + tig]);
                a[mt][1] = __float_as_uint(A[(m + 8) * ASTR + kh + tig]);
                a[mt][2] = __float_as_uint(A[m * ASTR + kh + tig + 4]);
                a[mt][3] = __float_as_uint(A[(m + 8) * ASTR + kh + tig + 4]);
            }
#pragma unroll
            for (int nt = 0; nt < 4; nt++) {
                const int n = wn + nt * 8 + g;
                b[nt][0] = __float_as_uint(B[(kh + tig) * EBSTR + n]);
                b[nt][1] = __float_as_uint(B[(kh + tig + 4) * EBSTR + n]);
            }
#pragma unroll
            for (int mt = 0; mt < 4; mt++)
#pragma unroll
                for (int nt = 0; nt < 4; nt++)
                    mma_tf32(c[mt][nt], a[mt], b[nt]);
        }
    }

    const int bb = blockIdx.x >> 2;
#pragma unroll
    for (int mt = 0; mt < 4; mt++) {
        const int jr = wm + mt * 16 + g;
        const float bv0 = b1v[jr];
        const float bv1 = b1v[jr + 8];
        float s0 = 0.f, s1 = 0.f;
#pragma unroll
        for (int nt = 0; nt < 4; nt++) {
            float e;
            e = c[mt][nt][0] + bv0; s0 += (e >= 0.f) ? e : 0.2f * e;
            e = c[mt][nt][1] + bv0; s0 += (e >= 0.f) ? e : 0.2f * e;
            e = c[mt][nt][2] + bv1; s1 += (e >= 0.f) ? e : 0.2f * e;
            e = c[mt][nt][3] + bv1; s1 += (e >= 0.f) ? e : 0.2f * e;
        }
        s0 += __shfl_xor_sync(0xffffffffu, s0, 1);
        s0 += __shfl_xor_sync(0xffffffffu, s0, 2);
        s1 += __shfl_xor_sync(0xffffffffu, s1, 1);
        s1 += __shfl_xor_sync(0xffffffffu, s1, 2);
        if (tig == 0) {
            atomicAdd(&g_M[bb * DD + jr], s0);
            atomicAdd(&g_M[bb * DD + jr + 8], s1);
        }
    }
}

// ============================================================================
// Kernel 4: out[b][i] = (1/T) * sum_j g_M[b][j] * emb_w2[i][j] + emb_b2[i]
// ============================================================================
__global__ __launch_bounds__(128) void out_kernel(const float* __restrict__ w2,
                                                  const float* __restrict__ b2,
                                                  float* __restrict__ out)
{
    __shared__ float m[128];
    const int b = blockIdx.x;
    const int i = threadIdx.x;
    m[i] = g_M[b * DD + i] * (1.f / (float)TT);
    __syncthreads();
    float s = b2[i];
    const float* wr = w2 + i * DD;
#pragma unroll 16
    for (int j = 0; j < DD; j++) s = fmaf(m[j], wr[j], s);
    out[b * DD + i] = s;
}

// ----------------------------------------------------------------------------
extern "C" void kernel_launch(void* const* d_in, const int* in_sizes, int n_in,
                              void* d_out, int out_size)
{
    const float* x      = (const float*)d_in[0];
    const float* fc1_w  = (const float*)d_in[1];
    const float* fc1_b  = (const float*)d_in[2];
    const float* wih_f  = (const float*)d_in[3];
    const float* whh_f  = (const float*)d_in[4];
    const float* bih_f  = (const float*)d_in[5];
    const float* bhh_f  = (const float*)d_in[6];
    const float* wih_b  = (const float*)d_in[7];
    const float* whh_b  = (const float*)d_in[8];
    const float* bih_b  = (const float*)d_in[9];
    const float* bhh_b  = (const float*)d_in[10];
    const float* lout_w = (const float*)d_in[11];
    const float* lout_b = (const float*)d_in[12];
    const float* emb_w1 = (const float*)d_in[13];
    const float* emb_b1 = (const float*)d_in[14];
    const float* emb_w2 = (const float*)d_in[15];
    const float* emb_b2 = (const float*)d_in[16];
    float* out = (float*)d_out;

    cudaFuncSetAttribute(fc1_mma_kernel,
                         cudaFuncAttributeMaxDynamicSharedMemorySize, GSMEM_BYTES);
    cudaFuncSetAttribute(emb1_mma_kernel,
                         cudaFuncAttributeMaxDynamicSharedMemorySize, EMB_SMEM_B);

    fc1_mma_kernel<<<dim3(TT / 256, BB), 256, GSMEM_BYTES>>>(x, fc1_w, fc1_b);
    zero_kernel<<<(BB * DD + 255) / 256, 256>>>();
    lstm_kernel<<<dim3(NTOT / 256, 2), 128>>>(wih_f, whh_f, bih_f, bhh_f,
                                              wih_b, whh_b, bih_b, bhh_b,
                                              lout_w, lout_b);
    emb1_mma_kernel<<<NTOT / 128, 256, EMB_SMEM_B>>>(emb_w1, emb_b1);
    out_kernel<<<BB, 128>>>(emb_w2, emb_b2, out);
}

// round 10
// speedup vs baseline: 1.7313x; 1.0652x over previous
#include <cuda_runtime.h>
#include <cstdint>

// Problem constants
#define BB   64
#define TT   512
#define NTOT 32768      // BB*TT
#define FF   1024
#define DD   128

// Scratch (device globals; no allocation allowed)
__device__ float g_G[DD * NTOT];       // fc1 output, layout [d][n]
__device__ float g_Y[2 * DD * NTOT];   // rows 0..127: lw0*h_fwd+lb ; 128..255: lw1*h_bwd
__device__ float g_M[BB * DD];         // sum over t of lrelu(e1)
__device__ unsigned g_wb[(FF/2) * DD]; // fc1_w bf16x2, layout [k2][m] (k2 = k-pair)

// ---------------------------------------------------------------- helpers
__device__ __forceinline__ float mtanh(float x) {
    float y;
    asm("tanh.approx.f32 %0, %1;" : "=f"(y) : "f"(x));
    return y;
}
__device__ __forceinline__ unsigned sptr(const void* p) {
    return (unsigned)__cvta_generic_to_shared(p);
}
__device__ __forceinline__ void cp16(unsigned dst, const void* src) {
    asm volatile("cp.async.cg.shared.global [%0], [%1], 16;" :: "r"(dst), "l"(src));
}
#define CP_COMMIT() asm volatile("cp.async.commit_group;")
#define CP_WAIT1()  asm volatile("cp.async.wait_group 1;")

// pack two fp32 into bf16x2: lower 16 bits = keven, upper = kodd
__device__ __forceinline__ unsigned pack_bf2(float kodd, float keven) {
    unsigned d;
    asm("cvt.rn.bf16x2.f32 %0, %1, %2;" : "=r"(d) : "f"(kodd), "f"(keven));
    return d;
}

__device__ __forceinline__ void mma_bf16(float c[4], const unsigned a[4], const unsigned b[2]) {
    asm volatile(
        "mma.sync.aligned.m16n8k16.row.col.f32.bf16.bf16.f32 "
        "{%0,%1,%2,%3}, {%4,%5,%6,%7}, {%8,%9}, {%0,%1,%2,%3};"
        : "+f"(c[0]), "+f"(c[1]), "+f"(c[2]), "+f"(c[3])
        : "r"(a[0]), "r"(a[1]), "r"(a[2]), "r"(a[3]), "r"(b[0]), "r"(b[1]));
}
__device__ __forceinline__ void mma_tf32(float c[4], const unsigned a[4], const unsigned b[2]) {
    asm volatile(
        "mma.sync.aligned.m16n8k8.row.col.f32.tf32.tf32.f32 "
        "{%0,%1,%2,%3}, {%4,%5,%6,%7}, {%8,%9}, {%0,%1,%2,%3};"
        : "+f"(c[0]), "+f"(c[1]), "+f"(c[2]), "+f"(c[3])
        : "r"(a[0]), "r"(a[1]), "r"(a[2]), "r"(a[3]), "r"(b[0]), "r"(b[1]));
}

// ============================================================================
// Kernel 0: convert fc1_w to bf16x2, layout g_wb[k2][m].
// ============================================================================
__global__ __launch_bounds__(256) void prep_kernel(const float* __restrict__ w)
{
    const int idx = blockIdx.x * 256 + threadIdx.x;   // 0..65535
    const int k2 = idx >> 7;        // 0..511
    const int m  = idx & 127;       // 0..127
    const float w0 = w[m * FF + 2 * k2];
    const float w1 = w[m * FF + 2 * k2 + 1];
    g_wb[idx] = pack_bf2(w1, w0);
}

// ============================================================================
// Kernel 1: fc1 GEMM, pure bf16 HMMA (m16n8k16). CTA 128(M) x 256(N),
// 8 warps 2x4 (warp tile 64x64), BK=16 (8 packed k2-rows per stage).
// A: cp.async from g_wb (3-stage ring), layout [k2][m], stride 136.
// B: x pairs packed in-flight (register prefetch + STS), [k2][n], stride 264.
// ============================================================================
#define FAST 136                      // A smem k2-row stride (uints)
#define FBST 264                      // B smem k2-row stride (uints)
#define FA_U (8 * FAST)               // 1088 uints per A stage
#define FB_U (8 * FBST)               // 2112 uints per B stage
#define FC1_SMEM_B ((3 * FA_U + 2 * FB_U) * 4)   // 29952 bytes

__global__ __launch_bounds__(256, 1) void fc1_bf16_kernel(const float* __restrict__ x,
                                                          const float* __restrict__ bias)
{
    extern __shared__ __align__(16) unsigned smu[];
    unsigned* A_[3]; unsigned* B_[2];
#pragma unroll
    for (int i = 0; i < 3; i++) A_[i] = smu + i * FA_U;
#pragma unroll
    for (int i = 0; i < 2; i++) B_[i] = smu + 3 * FA_U + i * FB_U;

    const int tid  = threadIdx.x;
    const int lane = tid & 31;
    const int wid  = tid >> 5;
    const int g    = lane >> 2;
    const int tig  = lane & 3;
    const int wm   = (wid & 1) * 64;
    const int wn   = (wid >> 1) * 64;

    const int bt = blockIdx.y;
    const int t0 = blockIdx.x * 256;
    const float* xb = x + (size_t)bt * FF * TT;

    // fill mappings: warp w owns k2-row w of the stage
    const int kr = wid;               // 0..7
    const int mq = lane * 4;          // A: 4 uints per thread (covers m 0..127)
    const int n8 = lane * 8;          // B: 8 uints per thread (covers n 0..255)

    float c[4][8][4];
#pragma unroll
    for (int i = 0; i < 4; i++)
#pragma unroll
        for (int j = 0; j < 8; j++)
#pragma unroll
            for (int k = 0; k < 4; k++) c[i][j][k] = 0.f;

    const int NS = FF / 16;   // 64 stages

    // prologue: A stages 0,1 (cp.async), B stage 0 (registers)
#pragma unroll
    for (int s = 0; s < 2; s++) {
        cp16(sptr(A_[s] + kr * FAST + mq), g_wb + (s * 8 + kr) * 128 + mq);
        CP_COMMIT();
    }
    float4 u0, u1, v0, v1;
    {
        const float* xp = xb + (size_t)(2 * kr) * TT + t0 + n8;
        u0 = *reinterpret_cast<const float4*>(xp);
        u1 = *reinterpret_cast<const float4*>(xp + 4);
        v0 = *reinterpret_cast<const float4*>(xp + TT);
        v1 = *reinterpret_cast<const float4*>(xp + TT + 4);
    }

    for (int s = 0; s < NS; s++) {
        // pack + store B(s)
        {
            unsigned* bp = B_[s & 1] + kr * FBST + n8;
            const float ue[8] = {u0.x, u0.y, u0.z, u0.w, u1.x, u1.y, u1.z, u1.w};
            const float vo[8] = {v0.x, v0.y, v0.z, v0.w, v1.x, v1.y, v1.z, v1.w};
            unsigned h[8];
#pragma unroll
            for (int i = 0; i < 8; i++) h[i] = pack_bf2(vo[i], ue[i]);
            *reinterpret_cast<uint4*>(bp)     = make_uint4(h[0], h[1], h[2], h[3]);
            *reinterpret_cast<uint4*>(bp + 4) = make_uint4(h[4], h[5], h[6], h[7]);
        }
        CP_WAIT1();          // A(s) landed
        __syncthreads();     // B(s) visible; all warps past MMA(s-1)

        if (s + 2 < NS)
            cp16(sptr(A_[(s + 2) % 3] + kr * FAST + mq),
                 g_wb + ((s + 2) * 8 + kr) * 128 + mq);
        CP_COMMIT();

        // prefetch B(s+1) into registers
        {
            const int sn = (s + 1 < NS) ? s + 1 : s;
            const float* xp = xb + (size_t)(sn * 16 + 2 * kr) * TT + t0 + n8;
            u0 = *reinterpret_cast<const float4*>(xp);
            u1 = *reinterpret_cast<const float4*>(xp + 4);
            v0 = *reinterpret_cast<const float4*>(xp + TT);
            v1 = *reinterpret_cast<const float4*>(xp + TT + 4);
        }

        // MMAs: 32 per warp per stage (k16 each)
        const unsigned* A = A_[s % 3];
        const unsigned* B = B_[s & 1];
        unsigned a[4][4], b[8][2];
#pragma unroll
        for (int mt = 0; mt < 4; mt++) {
            const int m = wm + mt * 16 + g;
            a[mt][0] = A[tig * FAST + m];
            a[mt][1] = A[tig * FAST + m + 8];
            a[mt][2] = A[(tig + 4) * FAST + m];
            a[mt][3] = A[(tig + 4) * FAST + m + 8];
        }
#pragma unroll
        for (int nt = 0; nt < 8; nt++) {
            const int n = wn + nt * 8 + g;
            b[nt][0] = B[tig * FBST + n];
            b[nt][1] = B[(tig + 4) * FBST + n];
        }
#pragma unroll
        for (int mt = 0; mt < 4; mt++)
#pragma unroll
            for (int nt = 0; nt < 8; nt++)
                mma_bf16(c[mt][nt], a[mt], b[nt]);
    }

    // epilogue: add bias, store to g_G[d][n]
    const int nbase = bt * TT + t0 + wn;
#pragma unroll
    for (int mt = 0; mt < 4; mt++) {
        const int dr = wm + mt * 16 + g;
        const float bv0 = bias[dr];
        const float bv1 = bias[dr + 8];
#pragma unroll
        for (int nt = 0; nt < 8; nt++) {
            const int ncol = nbase + nt * 8 + 2 * tig;
            float2 w0 = make_float2(c[mt][nt][0] + bv0, c[mt][nt][1] + bv0);
            float2 w1 = make_float2(c[mt][nt][2] + bv1, c[mt][nt][3] + bv1);
            *reinterpret_cast<float2*>(g_G + (size_t)dr * NTOT + ncol) = w0;
            *reinterpret_cast<float2*>(g_G + (size_t)(dr + 8) * NTOT + ncol) = w1;
        }
    }
}

// ============================================================================
// Kernel 2: LSTM, 2 sequences per thread (float2), one direction per
// blockIdx.y, 8-deep register prefetch ring on g_G loads.
// ============================================================================
#define PF 8

__global__ __launch_bounds__(128) void lstm_kernel(
    const float* __restrict__ wih_f, const float* __restrict__ whh_f,
    const float* __restrict__ bih_f, const float* __restrict__ bhh_f,
    const float* __restrict__ wih_b, const float* __restrict__ whh_b,
    const float* __restrict__ bih_b, const float* __restrict__ bhh_b,
    const float* __restrict__ lout_w, const float* __restrict__ lout_b)
{
    const int n   = (blockIdx.x * 128 + threadIdx.x) * 2;
    const int dir = blockIdx.y;

    const float* wih = dir ? wih_b : wih_f;
    const float* whh = dir ? whh_b : whh_f;
    const float* bih = dir ? bih_b : bih_f;
    const float* bhh = dir ? bhh_b : bhh_f;

    const float wi0 = 0.5f * wih[0], wh0 = 0.5f * whh[0], b0 = 0.5f * (bih[0] + bhh[0]);
    const float wi1 = 0.5f * wih[1], wh1 = 0.5f * whh[1], b1 = 0.5f * (bih[1] + bhh[1]);
    const float wi2 =        wih[2], wh2 =        whh[2], b2 =        (bih[2] + bhh[2]);
    const float wi3 = 0.5f * wih[3], wh3 = 0.5f * whh[3], b3 = 0.5f * (bih[3] + bhh[3]);

    const float lw = dir ? lout_w[1] : lout_w[0];
    const float lb = dir ? 0.f : lout_b[0];

    const int d0   = dir ? DD - 1 : 0;
    const int dstp = dir ? -1 : 1;
    const size_t ybase = dir ? (size_t)DD * NTOT : 0;

    float hx = 0.f, cx = 0.f, hy = 0.f, cy = 0.f;

    float2 q[PF];
#pragma unroll
    for (int p = 0; p < PF; p++)
        q[p] = *reinterpret_cast<const float2*>(g_G + (size_t)(d0 + dstp * p) * NTOT + n);

#pragma unroll 8
    for (int it = 0; it < DD; it++) {
        const int d = d0 + dstp * it;
        const float2 xv = q[it % PF];
        if (it + PF < DD)
            q[it % PF] = *reinterpret_cast<const float2*>(
                g_G + (size_t)(d0 + dstp * (it + PF)) * NTOT + n);

        const float aix = fmaf(wi0, xv.x, fmaf(wh0, hx, b0));
        const float aiy = fmaf(wi0, xv.y, fmaf(wh0, hy, b0));
        const float afx = fmaf(wi1, xv.x, fmaf(wh1, hx, b1));
        const float afy = fmaf(wi1, xv.y, fmaf(wh1, hy, b1));
        const float agx = fmaf(wi2, xv.x, fmaf(wh2, hx, b2));
        const float agy = fmaf(wi2, xv.y, fmaf(wh2, hy, b2));
        const float aox = fmaf(wi3, xv.x, fmaf(wh3, hx, b3));
        const float aoy = fmaf(wi3, xv.y, fmaf(wh3, hy, b3));

        const float six = fmaf(0.5f, mtanh(aix), 0.5f);
        const float siy = fmaf(0.5f, mtanh(aiy), 0.5f);
        const float sfx = fmaf(0.5f, mtanh(afx), 0.5f);
        const float sfy = fmaf(0.5f, mtanh(afy), 0.5f);
        const float tgx = mtanh(agx);
        const float tgy = mtanh(agy);
        const float sox = fmaf(0.5f, mtanh(aox), 0.5f);
        const float soy = fmaf(0.5f, mtanh(aoy), 0.5f);

        cx = fmaf(sfx, cx, six * tgx);
        cy = fmaf(sfy, cy, siy * tgy);
        hx = sox * mtanh(cx);
        hy = soy * mtanh(cy);

        float2 yv = make_float2(fmaf(lw, hx, lb), fmaf(lw, hy, lb));
        *reinterpret_cast<float2*>(g_Y + ybase + (size_t)d * NTOT + n) = yv;
    }
}

// ============================================================================
// Kernel 3a: zero the mean accumulator.
// ============================================================================
__global__ void zero_kernel()
{
    const int i = blockIdx.x * blockDim.x + threadIdx.x;
    if (i < BB * DD) g_M[i] = 0.f;
}

// ============================================================================
// Kernel 3b: e1 = (Yf+Yb)^T @ w1^T + b1 (tf32, K=128, Yf+Yb summed during
// the B fill), lrelu, sum over t -> atomicAdd g_M.
// ============================================================================
#define ASTR 20
#define EBSTR 136
#define EA_U (128 * ASTR)
#define EB_U (16 * EBSTR)
#define EMB_SMEM_B ((3 * EA_U + 2 * EB_U) * 4)

__global__ __launch_bounds__(256) void emb1_mma_kernel(const float* __restrict__ w1,
                                                       const float* __restrict__ b1v)
{
    extern __shared__ __align__(16) float sme[];
    float* As[3]; float* Bs[2];
#pragma unroll
    for (int i = 0; i < 3; i++) As[i] = sme + i * EA_U;
#pragma unroll
    for (int i = 0; i < 2; i++) Bs[i] = sme + 3 * EA_U + i * EB_U;

    const int tid  = threadIdx.x;
    const int lane = tid & 31;
    const int wid  = tid >> 5;
    const int g    = lane >> 2;
    const int tig  = lane & 3;
    const int wm   = (wid & 1) * 64;
    const int wn   = (wid >> 1) * 32;

    const int n0 = blockIdx.x * 128;

    const int rowA = tid >> 1;
    const int colA = (tid & 1) * 8;
    const int kr   = tid >> 4;
    const int n8   = (tid & 15) * 8;

    float c[4][4][4];
#pragma unroll
    for (int i = 0; i < 4; i++)
#pragma unroll
        for (int j = 0; j < 4; j++)
#pragma unroll
            for (int k = 0; k < 4; k++) c[i][j][k] = 0.f;

    const int NS = DD / 16;   // 8 stages

#pragma unroll
    for (int s = 0; s < 2; s++) {
        const float* wp = w1 + (size_t)rowA * DD + s * 16 + colA;
        cp16(sptr(As[s] + rowA * ASTR + colA), wp);
        cp16(sptr(As[s] + rowA * ASTR + colA + 4), wp + 4);
        CP_COMMIT();
    }
    float4 f0, f1, r0, r1;
    {
        const float* yf = g_Y + (size_t)kr * NTOT + n0 + n8;
        const float* yb = yf + (size_t)DD * NTOT;
        f0 = *reinterpret_cast<const float4*>(yf);
        f1 = *reinterpret_cast<const float4*>(yf + 4);
        r0 = *reinterpret_cast<const float4*>(yb);
        r1 = *reinterpret_cast<const float4*>(yb + 4);
    }

    for (int s = 0; s < NS; s++) {
        {
            float* bp = Bs[s & 1] + kr * EBSTR + n8;
            float4 s0 = make_float4(f0.x + r0.x, f0.y + r0.y, f0.z + r0.z, f0.w + r0.w);
            float4 s1 = make_float4(f1.x + r1.x, f1.y + r1.y, f1.z + r1.z, f1.w + r1.w);
            *reinterpret_cast<float4*>(bp)     = s0;
            *reinterpret_cast<float4*>(bp + 4) = s1;
        }
        CP_WAIT1();
        __syncthreads();

        if (s + 2 < NS) {
            const int sb = (s + 2) % 3;
            const float* wp = w1 + (size_t)rowA * DD + (s + 2) * 16 + colA;
            cp16(sptr(As[sb] + rowA * ASTR + colA), wp);
            cp16(sptr(As[sb] + rowA * ASTR + colA + 4), wp + 4);
        }
        CP_COMMIT();

        {
            const int sn = (s + 1 < NS) ? s + 1 : s;
            const float* yf = g_Y + (size_t)(sn * 16 + kr) * NTOT + n0 + n8;
            const float* yb = yf + (size_t)DD * NTOT;
            f0 = *reinterpret_cast<const float4*>(yf);
            f1 = *reinterpret_cast<const float4*>(yf + 4);
            r0 = *reinterpret_cast<const float4*>(yb);
            r1 = *reinterpret_cast<const float4*>(yb + 4);
        }

        const float* A = As[s % 3];
        const float* B = Bs[s & 1];
#pragma unroll
        for (int kh = 0; kh < 16; kh += 8) {
            unsigned a[4][4], b[4][2];
#pragma unroll
            for (int mt = 0; mt < 4; mt++) {
                const int m = wm + mt * 16 + g;
                a[mt][0] = __float_as_uint(A[m * ASTR + kh + tig]);
                a[mt][1] = __float_as_uint(A[(m + 8) * ASTR + kh + tig]);
                a[mt][2] = __float_as_uint(A[m * ASTR + kh + tig + 4]);
                a[mt][3] = __float_as_uint(A[(m + 8) * ASTR + kh + tig + 4]);
            }
#pragma unroll
            for (int nt = 0; nt < 4; nt++) {
                const int n = wn + nt * 8 + g;
                b[nt][0] = __float_as_uint(B[(kh + tig) * EBSTR + n]);
                b[nt][1] = __float_as_uint(B[(kh + tig + 4) * EBSTR + n]);
            }
#pragma unroll
            for (int mt = 0; mt < 4; mt++)
#pragma unroll
                for (int nt = 0; nt < 4; nt++)
                    mma_tf32(c[mt][nt], a[mt], b[nt]);
        }
    }

    const int bb = blockIdx.x >> 2;
#pragma unroll
    for (int mt = 0; mt < 4; mt++) {
        const int jr = wm + mt * 16 + g;
        const float bv0 = b1v[jr];
        const float bv1 = b1v[jr + 8];
        float s0 = 0.f, s1 = 0.f;
#pragma unroll
        for (int nt = 0; nt < 4; nt++) {
            float e;
            e = c[mt][nt][0] + bv0; s0 += (e >= 0.f) ? e : 0.2f * e;
            e = c[mt][nt][1] + bv0; s0 += (e >= 0.f) ? e : 0.2f * e;
            e = c[mt][nt][2] + bv1; s1 += (e >= 0.f) ? e : 0.2f * e;
            e = c[mt][nt][3] + bv1; s1 += (e >= 0.f) ? e : 0.2f * e;
        }
        s0 += __shfl_xor_sync(0xffffffffu, s0, 1);
        s0 += __shfl_xor_sync(0xffffffffu, s0, 2);
        s1 += __shfl_xor_sync(0xffffffffu, s1, 1);
        s1 += __shfl_xor_sync(0xffffffffu, s1, 2);
        if (tig == 0) {
            atomicAdd(&g_M[bb * DD + jr], s0);
            atomicAdd(&g_M[bb * DD + jr + 8], s1);
        }
    }
}

// ============================================================================
// Kernel 4: out[b][i] = (1/T) * sum_j g_M[b][j] * emb_w2[i][j] + emb_b2[i]
// ============================================================================
__global__ __launch_bounds__(128) void out_kernel(const float* __restrict__ w2,
                                                  const float* __restrict__ b2,
                                                  float* __restrict__ out)
{
    __shared__ float m[128];
    const int b = blockIdx.x;
    const int i = threadIdx.x;
    m[i] = g_M[b * DD + i] * (1.f / (float)TT);
    __syncthreads();
    float s = b2[i];
    const float* wr = w2 + i * DD;
#pragma unroll 16
    for (int j = 0; j < DD; j++) s = fmaf(m[j], wr[j], s);
    out[b * DD + i] = s;
}

// ----------------------------------------------------------------------------
extern "C" void kernel_launch(void* const* d_in, const int* in_sizes, int n_in,
                              void* d_out, int out_size)
{
    const float* x      = (const float*)d_in[0];
    const float* fc1_w  = (const float*)d_in[1];
    const float* fc1_b  = (const float*)d_in[2];
    const float* wih_f  = (const float*)d_in[3];
    const float* whh_f  = (const float*)d_in[4];
    const float* bih_f  = (const float*)d_in[5];
    const float* bhh_f  = (const float*)d_in[6];
    const float* wih_b  = (const float*)d_in[7];
    const float* whh_b  = (const float*)d_in[8];
    const float* bih_b  = (const float*)d_in[9];
    const float* bhh_b  = (const float*)d_in[10];
    const float* lout_w = (const float*)d_in[11];
    const float* lout_b = (const float*)d_in[12];
    const float* emb_w1 = (const float*)d_in[13];
    const float* emb_b1 = (const float*)d_in[14];
    const float* emb_w2 = (const float*)d_in[15];
    const float* emb_b2 = (const float*)d_in[16];
    float* out = (float*)d_out;

    cudaFuncSetAttribute(fc1_bf16_kernel,
                         cudaFuncAttributeMaxDynamicSharedMemorySize, FC1_SMEM_B);
    cudaFuncSetAttribute(emb1_mma_kernel,
                         cudaFuncAttributeMaxDynamicSharedMemorySize, EMB_SMEM_B);

    prep_kernel<<<256, 256>>>(fc1_w);
    zero_kernel<<<(BB * DD + 255) / 256, 256>>>();
    fc1_bf16_kernel<<<dim3(TT / 256, BB), 256, FC1_SMEM_B>>>(x, fc1_b);
    lstm_kernel<<<dim3(NTOT / 256, 2), 128>>>(wih_f, whh_f, bih_f, bhh_f,
                                              wih_b, whh_b, bih_b, bhh_b,
                                              lout_w, lout_b);
    emb1_mma_kernel<<<NTOT / 128, 256, EMB_SMEM_B>>>(emb_w1, emb_b1);
    out_kernel<<<BB, 128>>>(emb_w2, emb_b2, out);
}

// round 11
// speedup vs baseline: 1.9233x; 1.1109x over previous
#include <cuda_runtime.h>
#include <cstdint>

// Problem constants
#define BB   64
#define TT   512
#define NTOT 32768      // BB*TT
#define FF   1024
#define DD   128

// Scratch (device globals; no allocation allowed)
__device__ float g_G[DD * NTOT];       // fc1 output, layout [d][n]
__device__ float g_Y[2 * DD * NTOT];   // rows 0..127: lw0*h_fwd+lb ; 128..255: lw1*h_bwd
__device__ float g_M[BB * DD];         // sum over t of lrelu(e1)
__device__ unsigned g_wb[(FF/2) * DD]; // fc1_w bf16x2, layout [k2][m]

// ---------------------------------------------------------------- helpers
__device__ __forceinline__ float mtanh(float x) {
    float y;
    asm("tanh.approx.f32 %0, %1;" : "=f"(y) : "f"(x));
    return y;
}
__device__ __forceinline__ unsigned sptr(const void* p) {
    return (unsigned)__cvta_generic_to_shared(p);
}
__device__ __forceinline__ void cp16(unsigned dst, const void* src) {
    asm volatile("cp.async.cg.shared.global [%0], [%1], 16;" :: "r"(dst), "l"(src));
}
#define CP_COMMIT() asm volatile("cp.async.commit_group;")
#define CP_WAIT1()  asm volatile("cp.async.wait_group 1;")

__device__ __forceinline__ unsigned pack_bf2(float kodd, float keven) {
    unsigned d;
    asm("cvt.rn.bf16x2.f32 %0, %1, %2;" : "=r"(d) : "f"(kodd), "f"(keven));
    return d;
}

__device__ __forceinline__ void mma_bf16(float c[4], const unsigned a[4], const unsigned b[2]) {
    asm volatile(
        "mma.sync.aligned.m16n8k16.row.col.f32.bf16.bf16.f32 "
        "{%0,%1,%2,%3}, {%4,%5,%6,%7}, {%8,%9}, {%0,%1,%2,%3};"
        : "+f"(c[0]), "+f"(c[1]), "+f"(c[2]), "+f"(c[3])
        : "r"(a[0]), "r"(a[1]), "r"(a[2]), "r"(a[3]), "r"(b[0]), "r"(b[1]));
}
__device__ __forceinline__ void mma_tf32(float c[4], const unsigned a[4], const unsigned b[2]) {
    asm volatile(
        "mma.sync.aligned.m16n8k8.row.col.f32.tf32.tf32.f32 "
        "{%0,%1,%2,%3}, {%4,%5,%6,%7}, {%8,%9}, {%0,%1,%2,%3};"
        : "+f"(c[0]), "+f"(c[1]), "+f"(c[2]), "+f"(c[3])
        : "r"(a[0]), "r"(a[1]), "r"(a[2]), "r"(a[3]), "r"(b[0]), "r"(b[1]));
}

// ============================================================================
// Kernel 0: convert fc1_w to bf16x2, layout g_wb[k2][m].
// ============================================================================
__global__ __launch_bounds__(256) void prep_kernel(const float* __restrict__ w)
{
    const int idx = blockIdx.x * 256 + threadIdx.x;   // 0..65535
    const int k2 = idx >> 7;
    const int m  = idx & 127;
    const float w0 = w[m * FF + 2 * k2];
    const float w1 = w[m * FF + 2 * k2 + 1];
    g_wb[idx] = pack_bf2(w1, w0);
}

// ============================================================================
// Kernel 1: fc1 GEMM, bf16 HMMA (m16n8k16). CTA 128(M) x 128(N), BK=32
// (16 packed k2-rows/stage), 8 warps 2x4 (warp tile 64x32), 2 CTAs/SM.
// A: cp.async from g_wb (3-stage ring). B: x packed in-flight (2-stage).
// ============================================================================
#define FAST 136                      // smem k2-row stride (uints)
#define FA_U (16 * FAST)              // 2176 uints per A stage
#define FB_U (16 * FAST)              // 2176 uints per B stage
#define FC1_SMEM_B ((3 * FA_U + 2 * FB_U) * 4)   // 43520 bytes

__global__ __launch_bounds__(256, 2) void fc1_bf16_kernel(const float* __restrict__ x,
                                                          const float* __restrict__ bias)
{
    extern __shared__ __align__(16) unsigned smu[];
    unsigned* A_[3]; unsigned* B_[2];
#pragma unroll
    for (int i = 0; i < 3; i++) A_[i] = smu + i * FA_U;
#pragma unroll
    for (int i = 0; i < 2; i++) B_[i] = smu + 3 * FA_U + i * FB_U;

    const int tid  = threadIdx.x;
    const int lane = tid & 31;
    const int wid  = tid >> 5;
    const int g    = lane >> 2;
    const int tig  = lane & 3;
    const int wm   = (wid & 1) * 64;
    const int wn   = (wid >> 1) * 32;

    const int bt = blockIdx.y;
    const int t0 = blockIdx.x * 128;
    const float* xb = x + (size_t)bt * FF * TT;

    // fill mappings: 16 k2-rows per stage, 256 threads -> 8 uints each
    const int kr = tid >> 4;          // 0..15 (k2-row within stage)
    const int q8 = (tid & 15) * 8;    // 0..120 (column offset, m or n)

    float c[4][4][4];
#pragma unroll
    for (int i = 0; i < 4; i++)
#pragma unroll
        for (int j = 0; j < 4; j++)
#pragma unroll
            for (int k = 0; k < 4; k++) c[i][j][k] = 0.f;

    const int NS = FF / 32;   // 32 stages

    // prologue: A stages 0,1 via cp.async; B stage 0 into registers
#pragma unroll
    for (int s = 0; s < 2; s++) {
        cp16(sptr(A_[s] + kr * FAST + q8), g_wb + (s * 16 + kr) * 128 + q8);
        cp16(sptr(A_[s] + kr * FAST + q8 + 4), g_wb + (s * 16 + kr) * 128 + q8 + 4);
        CP_COMMIT();
    }
    float4 u0, u1, v0, v1;
    {
        const float* xp = xb + (size_t)(2 * kr) * TT + t0 + q8;
        u0 = *reinterpret_cast<const float4*>(xp);
        u1 = *reinterpret_cast<const float4*>(xp + 4);
        v0 = *reinterpret_cast<const float4*>(xp + TT);
        v1 = *reinterpret_cast<const float4*>(xp + TT + 4);
    }

    for (int s = 0; s < NS; s++) {
        // pack + store B(s)
        {
            unsigned* bp = B_[s & 1] + kr * FAST + q8;
            const float ue[8] = {u0.x, u0.y, u0.z, u0.w, u1.x, u1.y, u1.z, u1.w};
            const float vo[8] = {v0.x, v0.y, v0.z, v0.w, v1.x, v1.y, v1.z, v1.w};
            unsigned h[8];
#pragma unroll
            for (int i = 0; i < 8; i++) h[i] = pack_bf2(vo[i], ue[i]);
            *reinterpret_cast<uint4*>(bp)     = make_uint4(h[0], h[1], h[2], h[3]);
            *reinterpret_cast<uint4*>(bp + 4) = make_uint4(h[4], h[5], h[6], h[7]);
        }
        CP_WAIT1();          // A(s) landed
        __syncthreads();     // B(s) visible; all warps past MMA(s-1)

        if (s + 2 < NS) {
            const unsigned* wp = g_wb + ((s + 2) * 16 + kr) * 128 + q8;
            unsigned dst = sptr(A_[(s + 2) % 3] + kr * FAST + q8);
            cp16(dst, wp); cp16(dst + 16, wp + 4);
        }
        CP_COMMIT();

        // prefetch B(s+1) into registers
        {
            const int sn = (s + 1 < NS) ? s + 1 : s;
            const float* xp = xb + (size_t)(sn * 32 + 2 * kr) * TT + t0 + q8;
            u0 = *reinterpret_cast<const float4*>(xp);
            u1 = *reinterpret_cast<const float4*>(xp + 4);
            v0 = *reinterpret_cast<const float4*>(xp + TT);
            v1 = *reinterpret_cast<const float4*>(xp + TT + 4);
        }

        // MMAs: 2 k16-groups x 16 tiles per warp per stage
        const unsigned* A = A_[s % 3];
        const unsigned* B = B_[s & 1];
#pragma unroll
        for (int kb = 0; kb < 16; kb += 8) {
            unsigned a[4][4], b[4][2];
#pragma unroll
            for (int mt = 0; mt < 4; mt++) {
                const int m = wm + mt * 16 + g;
                a[mt][0] = A[(kb + tig) * FAST + m];
                a[mt][1] = A[(kb + tig) * FAST + m + 8];
                a[mt][2] = A[(kb + tig + 4) * FAST + m];
                a[mt][3] = A[(kb + tig + 4) * FAST + m + 8];
            }
#pragma unroll
            for (int nt = 0; nt < 4; nt++) {
                const int n = wn + nt * 8 + g;
                b[nt][0] = B[(kb + tig) * FAST + n];
                b[nt][1] = B[(kb + tig + 4) * FAST + n];
            }
#pragma unroll
            for (int mt = 0; mt < 4; mt++)
#pragma unroll
                for (int nt = 0; nt < 4; nt++)
                    mma_bf16(c[mt][nt], a[mt], b[nt]);
        }
    }

    // epilogue: add bias, store to g_G[d][n]
    const int nbase = bt * TT + t0 + wn;
#pragma unroll
    for (int mt = 0; mt < 4; mt++) {
        const int dr = wm + mt * 16 + g;
        const float bv0 = bias[dr];
        const float bv1 = bias[dr + 8];
#pragma unroll
        for (int nt = 0; nt < 4; nt++) {
            const int ncol = nbase + nt * 8 + 2 * tig;
            float2 w0 = make_float2(c[mt][nt][0] + bv0, c[mt][nt][1] + bv0);
            float2 w1 = make_float2(c[mt][nt][2] + bv1, c[mt][nt][3] + bv1);
            *reinterpret_cast<float2*>(g_G + (size_t)dr * NTOT + ncol) = w0;
            *reinterpret_cast<float2*>(g_G + (size_t)(dr + 8) * NTOT + ncol) = w1;
        }
    }
}

// ============================================================================
// Kernel 2: LSTM, 1 sequence per thread, 256 threads/CTA, one direction per
// blockIdx.y, 8-deep register prefetch ring on g_G loads (coalesced).
// ============================================================================
#define PF 8

__global__ __launch_bounds__(256) void lstm_kernel(
    const float* __restrict__ wih_f, const float* __restrict__ whh_f,
    const float* __restrict__ bih_f, const float* __restrict__ bhh_f,
    const float* __restrict__ wih_b, const float* __restrict__ whh_b,
    const float* __restrict__ bih_b, const float* __restrict__ bhh_b,
    const float* __restrict__ lout_w, const float* __restrict__ lout_b)
{
    const int n   = blockIdx.x * 256 + threadIdx.x;
    const int dir = blockIdx.y;

    const float* wih = dir ? wih_b : wih_f;
    const float* whh = dir ? whh_b : whh_f;
    const float* bih = dir ? bih_b : bih_f;
    const float* bhh = dir ? bhh_b : bhh_f;

    const float wi0 = 0.5f * wih[0], wh0 = 0.5f * whh[0], b0 = 0.5f * (bih[0] + bhh[0]);
    const float wi1 = 0.5f * wih[1], wh1 = 0.5f * whh[1], b1 = 0.5f * (bih[1] + bhh[1]);
    const float wi2 =        wih[2], wh2 =        whh[2], b2 =        (bih[2] + bhh[2]);
    const float wi3 = 0.5f * wih[3], wh3 = 0.5f * whh[3], b3 = 0.5f * (bih[3] + bhh[3]);

    const float lw = dir ? lout_w[1] : lout_w[0];
    const float lb = dir ? 0.f : lout_b[0];

    const int d0   = dir ? DD - 1 : 0;
    const int dstp = dir ? -1 : 1;
    const size_t ybase = dir ? (size_t)DD * NTOT : 0;

    float h = 0.f, c = 0.f;

    float q[PF];
#pragma unroll
    for (int p = 0; p < PF; p++)
        q[p] = g_G[(size_t)(d0 + dstp * p) * NTOT + n];

#pragma unroll 8
    for (int it = 0; it < DD; it++) {
        const int d = d0 + dstp * it;
        const float xv = q[it % PF];
        if (it + PF < DD)
            q[it % PF] = g_G[(size_t)(d0 + dstp * (it + PF)) * NTOT + n];

        const float ai = fmaf(wi0, xv, fmaf(wh0, h, b0));
        const float af = fmaf(wi1, xv, fmaf(wh1, h, b1));
        const float ag = fmaf(wi2, xv, fmaf(wh2, h, b2));
        const float ao = fmaf(wi3, xv, fmaf(wh3, h, b3));

        const float si = fmaf(0.5f, mtanh(ai), 0.5f);
        const float sf = fmaf(0.5f, mtanh(af), 0.5f);
        const float tg = mtanh(ag);
        const float so = fmaf(0.5f, mtanh(ao), 0.5f);

        c = fmaf(sf, c, si * tg);
        h = so * mtanh(c);

        g_Y[ybase + (size_t)d * NTOT + n] = fmaf(lw, h, lb);
    }
}

// ============================================================================
// Kernel 3a: zero the mean accumulator.
// ============================================================================
__global__ void zero_kernel()
{
    const int i = blockIdx.x * blockDim.x + threadIdx.x;
    if (i < BB * DD) g_M[i] = 0.f;
}

// ============================================================================
// Kernel 3b: e1 = (Yf+Yb)^T @ w1^T + b1 (tf32, K=128, Yf+Yb summed during
// the B fill), lrelu, sum over t -> atomicAdd g_M.
// ============================================================================
#define ASTR 20
#define EBSTR 136
#define EA_U (128 * ASTR)
#define EB_U (16 * EBSTR)
#define EMB_SMEM_B ((3 * EA_U + 2 * EB_U) * 4)

__global__ __launch_bounds__(256) void emb1_mma_kernel(const float* __restrict__ w1,
                                                       const float* __restrict__ b1v)
{
    extern __shared__ __align__(16) float sme[];
    float* As[3]; float* Bs[2];
#pragma unroll
    for (int i = 0; i < 3; i++) As[i] = sme + i * EA_U;
#pragma unroll
    for (int i = 0; i < 2; i++) Bs[i] = sme + 3 * EA_U + i * EB_U;

    const int tid  = threadIdx.x;
    const int lane = tid & 31;
    const int wid  = tid >> 5;
    const int g    = lane >> 2;
    const int tig  = lane & 3;
    const int wm   = (wid & 1) * 64;
    const int wn   = (wid >> 1) * 32;

    const int n0 = blockIdx.x * 128;

    const int rowA = tid >> 1;
    const int colA = (tid & 1) * 8;
    const int kr   = tid >> 4;
    const int n8   = (tid & 15) * 8;

    float c[4][4][4];
#pragma unroll
    for (int i = 0; i < 4; i++)
#pragma unroll
        for (int j = 0; j < 4; j++)
#pragma unroll
            for (int k = 0; k < 4; k++) c[i][j][k] = 0.f;

    const int NS = DD / 16;   // 8 stages

#pragma unroll
    for (int s = 0; s < 2; s++) {
        const float* wp = w1 + (size_t)rowA * DD + s * 16 + colA;
        cp16(sptr(As[s] + rowA * ASTR + colA), wp);
        cp16(sptr(As[s] + rowA * ASTR + colA + 4), wp + 4);
        CP_COMMIT();
    }
    float4 f0, f1, r0, r1;
    {
        const float* yf = g_Y + (size_t)kr * NTOT + n0 + n8;
        const float* yb = yf + (size_t)DD * NTOT;
        f0 = *reinterpret_cast<const float4*>(yf);
        f1 = *reinterpret_cast<const float4*>(yf + 4);
        r0 = *reinterpret_cast<const float4*>(yb);
        r1 = *reinterpret_cast<const float4*>(yb + 4);
    }

    for (int s = 0; s < NS; s++) {
        {
            float* bp = Bs[s & 1] + kr * EBSTR + n8;
            float4 s0 = make_float4(f0.x + r0.x, f0.y + r0.y, f0.z + r0.z, f0.w + r0.w);
            float4 s1 = make_float4(f1.x + r1.x, f1.y + r1.y, f1.z + r1.z, f1.w + r1.w);
            *reinterpret_cast<float4*>(bp)     = s0;
            *reinterpret_cast<float4*>(bp + 4) = s1;
        }
        CP_WAIT1();
        __syncthreads();

        if (s + 2 < NS) {
            const int sb = (s + 2) % 3;
            const float* wp = w1 + (size_t)rowA * DD + (s + 2) * 16 + colA;
            cp16(sptr(As[sb] + rowA * ASTR + colA), wp);
            cp16(sptr(As[sb] + rowA * ASTR + colA + 4), wp + 4);
        }
        CP_COMMIT();

        {
            const int sn = (s + 1 < NS) ? s + 1 : s;
            const float* yf = g_Y + (size_t)(sn * 16 + kr) * NTOT + n0 + n8;
            const float* yb = yf + (size_t)DD * NTOT;
            f0 = *reinterpret_cast<const float4*>(yf);
            f1 = *reinterpret_cast<const float4*>(yf + 4);
            r0 = *reinterpret_cast<const float4*>(yb);
            r1 = *reinterpret_cast<const float4*>(yb + 4);
        }

        const float* A = As[s % 3];
        const float* B = Bs[s & 1];
#pragma unroll
        for (int kh = 0; kh < 16; kh += 8) {
            unsigned a[4][4], b[4][2];
#pragma unroll
            for (int mt = 0; mt < 4; mt++) {
                const int m = wm + mt * 16 + g;
                a[mt][0] = __float_as_uint(A[m * ASTR + kh + tig]);
                a[mt][1] = __float_as_uint(A[(m + 8) * ASTR + kh + tig]);
                a[mt][2] = __float_as_uint(A[m * ASTR + kh + tig + 4]);
                a[mt][3] = __float_as_uint(A[(m + 8) * ASTR + kh + tig + 4]);
            }
#pragma unroll
            for (int nt = 0; nt < 4; nt++) {
                const int n = wn + nt * 8 + g;
                b[nt][0] = __float_as_uint(B[(kh + tig) * EBSTR + n]);
                b[nt][1] = __float_as_uint(B[(kh + tig + 4) * EBSTR + n]);
            }
#pragma unroll
            for (int mt = 0; mt < 4; mt++)
#pragma unroll
                for (int nt = 0; nt < 4; nt++)
                    mma_tf32(c[mt][nt], a[mt], b[nt]);
        }
    }

    const int bb = blockIdx.x >> 2;
#pragma unroll
    for (int mt = 0; mt < 4; mt++) {
        const int jr = wm + mt * 16 + g;
        const float bv0 = b1v[jr];
        const float bv1 = b1v[jr + 8];
        float s0 = 0.f, s1 = 0.f;
#pragma unroll
        for (int nt = 0; nt < 4; nt++) {
            float e;
            e = c[mt][nt][0] + bv0; s0 += (e >= 0.f) ? e : 0.2f * e;
            e = c[mt][nt][1] + bv0; s0 += (e >= 0.f) ? e : 0.2f * e;
            e = c[mt][nt][2] + bv1; s1 += (e >= 0.f) ? e : 0.2f * e;
            e = c[mt][nt][3] + bv1; s1 += (e >= 0.f) ? e : 0.2f * e;
        }
        s0 += __shfl_xor_sync(0xffffffffu, s0, 1);
        s0 += __shfl_xor_sync(0xffffffffu, s0, 2);
        s1 += __shfl_xor_sync(0xffffffffu, s1, 1);
        s1 += __shfl_xor_sync(0xffffffffu, s1, 2);
        if (tig == 0) {
            atomicAdd(&g_M[bb * DD + jr], s0);
            atomicAdd(&g_M[bb * DD + jr + 8], s1);
        }
    }
}

// ============================================================================
// Kernel 4: out[b][i] = (1/T) * sum_j g_M[b][j] * emb_w2[i][j] + emb_b2[i]
// ============================================================================
__global__ __launch_bounds__(128) void out_kernel(const float* __restrict__ w2,
                                                  const float* __restrict__ b2,
                                                  float* __restrict__ out)
{
    __shared__ float m[128];
    const int b = blockIdx.x;
    const int i = threadIdx.x;
    m[i] = g_M[b * DD + i] * (1.f / (float)TT);
    __syncthreads();
    float s = b2[i];
    const float* wr = w2 + i * DD;
#pragma unroll 16
    for (int j = 0; j < DD; j++) s = fmaf(m[j], wr[j], s);
    out[b * DD + i] = s;
}

// ----------------------------------------------------------------------------
extern "C" void kernel_launch(void* const* d_in, const int* in_sizes, int n_in,
                              void* d_out, int out_size)
{
    const float* x      = (const float*)d_in[0];
    const float* fc1_w  = (const float*)d_in[1];
    const float* fc1_b  = (const float*)d_in[2];
    const float* wih_f  = (const float*)d_in[3];
    const float* whh_f  = (const float*)d_in[4];
    const float* bih_f  = (const float*)d_in[5];
    const float* bhh_f  = (const float*)d_in[6];
    const float* wih_b  = (const float*)d_in[7];
    const float* whh_b  = (const float*)d_in[8];
    const float* bih_b  = (const float*)d_in[9];
    const float* bhh_b  = (const float*)d_in[10];
    const float* lout_w = (const float*)d_in[11];
    const float* lout_b = (const float*)d_in[12];
    const float* emb_w1 = (const float*)d_in[13];
    const float* emb_b1 = (const float*)d_in[14];
    const float* emb_w2 = (const float*)d_in[15];
    const float* emb_b2 = (const float*)d_in[16];
    float* out = (float*)d_out;

    cudaFuncSetAttribute(fc1_bf16_kernel,
                         cudaFuncAttributeMaxDynamicSharedMemorySize, FC1_SMEM_B);
    cudaFuncSetAttribute(emb1_mma_kernel,
                         cudaFuncAttributeMaxDynamicSharedMemorySize, EMB_SMEM_B);

    prep_kernel<<<256, 256>>>(fc1_w);
    zero_kernel<<<(BB * DD + 255) / 256, 256>>>();
    fc1_bf16_kernel<<<dim3(TT / 128, BB), 256, FC1_SMEM_B>>>(x, fc1_b);
    lstm_kernel<<<dim3(NTOT / 256, 2), 256>>>(wih_f, whh_f, bih_f, bhh_f,
                                              wih_b, whh_b, bih_b, bhh_b,
                                              lout_w, lout_b);
    emb1_mma_kernel<<<NTOT / 128, 256, EMB_SMEM_B>>>(emb_w1, emb_b1);
    out_kernel<<<BB, 128>>>(emb_w2, emb_b2, out);
}

// round 12
// speedup vs baseline: 2.2025x; 1.1451x over previous
#include <cuda_runtime.h>
#include <cstdint>

// Problem constants
#define BB   64
#define TT   512
#define NTOT 32768      // BB*TT
#define FF   1024
#define DD   128

// Scratch (device globals; no allocation allowed)
__device__ float g_G[DD * NTOT];       // fc1 output, layout [d][n]
__device__ float g_Y[2 * DD * NTOT];   // rows 0..127: lw0*h_fwd+lb ; 128..255: lw1*h_bwd
__device__ float g_M[BB * DD];         // sum over t of lrelu(e1)
__device__ unsigned g_wb[DD * (FF/2)]; // fc1_w bf16x2, layout [m][k2]

// ---------------------------------------------------------------- helpers
__device__ __forceinline__ float mtanh(float x) {
    float y;
    asm("tanh.approx.f32 %0, %1;" : "=f"(y) : "f"(x));
    return y;
}
__device__ __forceinline__ unsigned sptr(const void* p) {
    return (unsigned)__cvta_generic_to_shared(p);
}
__device__ __forceinline__ void cp16(unsigned dst, const void* src) {
    asm volatile("cp.async.cg.shared.global [%0], [%1], 16;" :: "r"(dst), "l"(src));
}
#define CP_COMMIT() asm volatile("cp.async.commit_group;")
#define CP_WAIT1()  asm volatile("cp.async.wait_group 1;")

__device__ __forceinline__ unsigned pack_bf2(float kodd, float keven) {
    unsigned d;
    asm("cvt.rn.bf16x2.f32 %0, %1, %2;" : "=r"(d) : "f"(kodd), "f"(keven));
    return d;
}
__device__ __forceinline__ void ldsm_x4(unsigned r[4], unsigned addr) {
    asm volatile("ldmatrix.sync.aligned.m8n8.x4.shared.b16 {%0,%1,%2,%3}, [%4];"
                 : "=r"(r[0]), "=r"(r[1]), "=r"(r[2]), "=r"(r[3]) : "r"(addr));
}

__device__ __forceinline__ void mma_bf16(float c[4], const unsigned a[4], const unsigned b[2]) {
    asm volatile(
        "mma.sync.aligned.m16n8k16.row.col.f32.bf16.bf16.f32 "
        "{%0,%1,%2,%3}, {%4,%5,%6,%7}, {%8,%9}, {%0,%1,%2,%3};"
        : "+f"(c[0]), "+f"(c[1]), "+f"(c[2]), "+f"(c[3])
        : "r"(a[0]), "r"(a[1]), "r"(a[2]), "r"(a[3]), "r"(b[0]), "r"(b[1]));
}
__device__ __forceinline__ void mma_tf32(float c[4], const unsigned a[4], const unsigned b[2]) {
    asm volatile(
        "mma.sync.aligned.m16n8k8.row.col.f32.tf32.tf32.f32 "
        "{%0,%1,%2,%3}, {%4,%5,%6,%7}, {%8,%9}, {%0,%1,%2,%3};"
        : "+f"(c[0]), "+f"(c[1]), "+f"(c[2]), "+f"(c[3])
        : "r"(a[0]), "r"(a[1]), "r"(a[2]), "r"(a[3]), "r"(b[0]), "r"(b[1]));
}

// ============================================================================
// Kernel 0: convert fc1_w to bf16x2 (layout [m][k2]) and zero g_M.
// ============================================================================
__global__ __launch_bounds__(256) void prep_kernel(const float* __restrict__ w)
{
    const int idx = blockIdx.x * 256 + threadIdx.x;   // 0..65535
    const int m  = idx >> 9;        // 0..127
    const int k2 = idx & 511;       // 0..511
    const float w0 = w[m * FF + 2 * k2];
    const float w1 = w[m * FF + 2 * k2 + 1];
    g_wb[m * 512 + k2] = pack_bf2(w1, w0);
    if (idx < BB * DD) g_M[idx] = 0.f;
}

// ============================================================================
// Kernel 1: fc1 GEMM, bf16 HMMA (m16n8k16). CTA 128(M) x 128(N), BK=32,
// 8 warps 2x4 (warp tile 64x32), 2 CTAs/SM.
// A: [m][k2] rows (stride 20 uints), cp.async 3-ring, drained via ldmatrix.x4.
// B: [k2][n] (stride 136), x packed in-flight, drained via scalar LDS.
// ============================================================================
#define AMST 20                       // A smem m-row stride (uints)
#define BKST 136                      // B smem k2-row stride (uints)
#define FA_U (128 * AMST)             // 2560 uints per A stage
#define FB_U (16 * BKST)              // 2176 uints per B stage
#define FC1_SMEM_B ((3 * FA_U + 2 * FB_U) * 4)   // 48128 bytes

__global__ __launch_bounds__(256, 2) void fc1_bf16_kernel(const float* __restrict__ x,
                                                          const float* __restrict__ bias)
{
    extern __shared__ __align__(16) unsigned smu[];
    unsigned* A_[3]; unsigned* B_[2];
#pragma unroll
    for (int i = 0; i < 3; i++) A_[i] = smu + i * FA_U;
#pragma unroll
    for (int i = 0; i < 2; i++) B_[i] = smu + 3 * FA_U + i * FB_U;

    const int tid  = threadIdx.x;
    const int lane = tid & 31;
    const int wid  = tid >> 5;
    const int g    = lane >> 2;
    const int tig  = lane & 3;
    const int wm   = (wid & 1) * 64;
    const int wn   = (wid >> 1) * 32;

    const int bt = blockIdx.y;
    const int t0 = blockIdx.x * 128;
    const float* xb = x + (size_t)bt * FF * TT;

    // A fill: 2 threads per m-row, 8 uints each (2 cp16)
    const int rowA  = tid >> 1;
    const int halfA = (tid & 1) * 8;
    // B fill: thread owns k2-row kr, 8 n-values
    const int kr = tid >> 4;          // 0..15
    const int q8 = (tid & 15) * 8;    // 0..120

    // LDSM lane address components (within A stage)
    const unsigned lrow = wm + (lane & 7) + ((lane >> 3) & 1) * 8;
    const unsigned lak  = ((lane >> 4) & 1) * 4;

    float c[4][4][4];
#pragma unroll
    for (int i = 0; i < 4; i++)
#pragma unroll
        for (int j = 0; j < 4; j++)
#pragma unroll
            for (int k = 0; k < 4; k++) c[i][j][k] = 0.f;

    const int NS = FF / 32;   // 32 stages

    // prologue: A stages 0,1 via cp.async; B stage 0 into registers
#pragma unroll
    for (int s = 0; s < 2; s++) {
        const unsigned* srcA = g_wb + rowA * 512 + s * 16 + halfA;
        unsigned dst = sptr(A_[s] + rowA * AMST + halfA);
        cp16(dst, srcA); cp16(dst + 16, srcA + 4);
        CP_COMMIT();
    }
    float4 u0, u1, v0, v1;
    {
        const float* xp = xb + (size_t)(2 * kr) * TT + t0 + q8;
        u0 = *reinterpret_cast<const float4*>(xp);
        u1 = *reinterpret_cast<const float4*>(xp + 4);
        v0 = *reinterpret_cast<const float4*>(xp + TT);
        v1 = *reinterpret_cast<const float4*>(xp + TT + 4);
    }

    for (int s = 0; s < NS; s++) {
        // pack + store B(s)
        {
            unsigned* bp = B_[s & 1] + kr * BKST + q8;
            const float ue[8] = {u0.x, u0.y, u0.z, u0.w, u1.x, u1.y, u1.z, u1.w};
            const float vo[8] = {v0.x, v0.y, v0.z, v0.w, v1.x, v1.y, v1.z, v1.w};
            unsigned h[8];
#pragma unroll
            for (int i = 0; i < 8; i++) h[i] = pack_bf2(vo[i], ue[i]);
            *reinterpret_cast<uint4*>(bp)     = make_uint4(h[0], h[1], h[2], h[3]);
            *reinterpret_cast<uint4*>(bp + 4) = make_uint4(h[4], h[5], h[6], h[7]);
        }
        CP_WAIT1();          // A(s) landed
        __syncthreads();     // B(s) visible; all warps past MMA(s-1)

        if (s + 2 < NS) {
            const unsigned* srcA = g_wb + rowA * 512 + (s + 2) * 16 + halfA;
            unsigned dst = sptr(A_[(s + 2) % 3] + rowA * AMST + halfA);
            cp16(dst, srcA); cp16(dst + 16, srcA + 4);
        }
        CP_COMMIT();

        // prefetch B(s+1) into registers
        {
            const int sn = (s + 1 < NS) ? s + 1 : s;
            const float* xp = xb + (size_t)(sn * 32 + 2 * kr) * TT + t0 + q8;
            u0 = *reinterpret_cast<const float4*>(xp);
            u1 = *reinterpret_cast<const float4*>(xp + 4);
            v0 = *reinterpret_cast<const float4*>(xp + TT);
            v1 = *reinterpret_cast<const float4*>(xp + TT + 4);
        }

        // MMAs: per g16 group: 4 LDSM.x4 (A) + 16 LDS (B) + 16 HMMA
        const unsigned Abase = sptr(A_[s % 3]);
        const unsigned* B = B_[s & 1];
#pragma unroll
        for (int g16 = 0; g16 < 2; g16++) {
            unsigned a[4][4], b[4][2];
#pragma unroll
            for (int mt = 0; mt < 4; mt++) {
                const unsigned ad = Abase +
                    ((lrow + mt * 16) * AMST + g16 * 8 + lak) * 4;
                ldsm_x4(a[mt], ad);
            }
#pragma unroll
            for (int nt = 0; nt < 4; nt++) {
                const int n = wn + nt * 8 + g;
                b[nt][0] = B[(g16 * 8 + tig) * BKST + n];
                b[nt][1] = B[(g16 * 8 + tig + 4) * BKST + n];
            }
#pragma unroll
            for (int mt = 0; mt < 4; mt++)
#pragma unroll
                for (int nt = 0; nt < 4; nt++)
                    mma_bf16(c[mt][nt], a[mt], b[nt]);
        }
    }

    // epilogue: add bias, store to g_G[d][n]
    const int nbase = bt * TT + t0 + wn;
#pragma unroll
    for (int mt = 0; mt < 4; mt++) {
        const int dr = wm + mt * 16 + g;
        const float bv0 = bias[dr];
        const float bv1 = bias[dr + 8];
#pragma unroll
        for (int nt = 0; nt < 4; nt++) {
            const int ncol = nbase + nt * 8 + 2 * tig;
            float2 w0 = make_float2(c[mt][nt][0] + bv0, c[mt][nt][1] + bv0);
            float2 w1 = make_float2(c[mt][nt][2] + bv1, c[mt][nt][3] + bv1);
            *reinterpret_cast<float2*>(g_G + (size_t)dr * NTOT + ncol) = w0;
            *reinterpret_cast<float2*>(g_G + (size_t)(dr + 8) * NTOT + ncol) = w1;
        }
    }
}

// ============================================================================
// Kernel 2: LSTM, 1 sequence per thread, pointer-walk addressing,
// 8-deep register prefetch ring. One direction per blockIdx.y.
// ============================================================================
#define PF 8

__global__ __launch_bounds__(256) void lstm_kernel(
    const float* __restrict__ wih_f, const float* __restrict__ whh_f,
    const float* __restrict__ bih_f, const float* __restrict__ bhh_f,
    const float* __restrict__ wih_b, const float* __restrict__ whh_b,
    const float* __restrict__ bih_b, const float* __restrict__ bhh_b,
    const float* __restrict__ lout_w, const float* __restrict__ lout_b)
{
    const int n   = blockIdx.x * 256 + threadIdx.x;
    const int dir = blockIdx.y;

    const float* wih = dir ? wih_b : wih_f;
    const float* whh = dir ? whh_b : whh_f;
    const float* bih = dir ? bih_b : bih_f;
    const float* bhh = dir ? bhh_b : bhh_f;

    const float wi0 = 0.5f * wih[0], wh0 = 0.5f * whh[0], b0 = 0.5f * (bih[0] + bhh[0]);
    const float wi1 = 0.5f * wih[1], wh1 = 0.5f * whh[1], b1 = 0.5f * (bih[1] + bhh[1]);
    const float wi2 =        wih[2], wh2 =        whh[2], b2 =        (bih[2] + bhh[2]);
    const float wi3 = 0.5f * wih[3], wh3 = 0.5f * whh[3], b3 = 0.5f * (bih[3] + bhh[3]);

    const float lw = dir ? lout_w[1] : lout_w[0];
    const float lb = dir ? 0.f : lout_b[0];

    const int d0 = dir ? DD - 1 : 0;
    const long stp = dir ? -(long)NTOT : (long)NTOT;

    const float* pf = g_G + (size_t)d0 * NTOT + n;      // prefetch cursor
    float* yp = g_Y + (dir ? (size_t)DD * NTOT : 0) + (size_t)d0 * NTOT + n;

    float h = 0.f, c = 0.f;

    float q[PF];
#pragma unroll
    for (int p = 0; p < PF; p++) { q[p] = *pf; pf += stp; }

#pragma unroll 8
    for (int it = 0; it < DD; it++) {
        const float xv = q[it % PF];
        if (it + PF < DD) { q[it % PF] = *pf; pf += stp; }

        const float ai = fmaf(wi0, xv, fmaf(wh0, h, b0));
        const float af = fmaf(wi1, xv, fmaf(wh1, h, b1));
        const float ag = fmaf(wi2, xv, fmaf(wh2, h, b2));
        const float ao = fmaf(wi3, xv, fmaf(wh3, h, b3));

        const float si = fmaf(0.5f, mtanh(ai), 0.5f);
        const float sf = fmaf(0.5f, mtanh(af), 0.5f);
        const float tg = mtanh(ag);
        const float so = fmaf(0.5f, mtanh(ao), 0.5f);

        c = fmaf(sf, c, si * tg);
        h = so * mtanh(c);

        *yp = fmaf(lw, h, lb);
        yp += stp;
    }
}

// ============================================================================
// Kernel 3: e1 = (Yf+Yb)^T @ w1^T + b1 (tf32, K=128, Yf+Yb summed during
// the B fill), lrelu, sum over t -> atomicAdd g_M.
// ============================================================================
#define ASTR 20
#define EBSTR 136
#define EA_U (128 * ASTR)
#define EB_U (16 * EBSTR)
#define EMB_SMEM_B ((3 * EA_U + 2 * EB_U) * 4)

__global__ __launch_bounds__(256) void emb1_mma_kernel(const float* __restrict__ w1,
                                                       const float* __restrict__ b1v)
{
    extern __shared__ __align__(16) float sme[];
    float* As[3]; float* Bs[2];
#pragma unroll
    for (int i = 0; i < 3; i++) As[i] = sme + i * EA_U;
#pragma unroll
    for (int i = 0; i < 2; i++) Bs[i] = sme + 3 * EA_U + i * EB_U;

    const int tid  = threadIdx.x;
    const int lane = tid & 31;
    const int wid  = tid >> 5;
    const int g    = lane >> 2;
    const int tig  = lane & 3;
    const int wm   = (wid & 1) * 64;
    const int wn   = (wid >> 1) * 32;

    const int n0 = blockIdx.x * 128;

    const int rowA = tid >> 1;
    const int colA = (tid & 1) * 8;
    const int kr   = tid >> 4;
    const int n8   = (tid & 15) * 8;

    float c[4][4][4];
#pragma unroll
    for (int i = 0; i < 4; i++)
#pragma unroll
        for (int j = 0; j < 4; j++)
#pragma unroll
            for (int k = 0; k < 4; k++) c[i][j][k] = 0.f;

    const int NS = DD / 16;   // 8 stages

#pragma unroll
    for (int s = 0; s < 2; s++) {
        const float* wp = w1 + (size_t)rowA * DD + s * 16 + colA;
        cp16(sptr(As[s] + rowA * ASTR + colA), wp);
        cp16(sptr(As[s] + rowA * ASTR + colA + 4), wp + 4);
        CP_COMMIT();
    }
    float4 f0, f1, r0, r1;
    {
        const float* yf = g_Y + (size_t)kr * NTOT + n0 + n8;
        const float* yb = yf + (size_t)DD * NTOT;
        f0 = *reinterpret_cast<const float4*>(yf);
        f1 = *reinterpret_cast<const float4*>(yf + 4);
        r0 = *reinterpret_cast<const float4*>(yb);
        r1 = *reinterpret_cast<const float4*>(yb + 4);
    }

    for (int s = 0; s < NS; s++) {
        {
            float* bp = Bs[s & 1] + kr * EBSTR + n8;
            float4 s0 = make_float4(f0.x + r0.x, f0.y + r0.y, f0.z + r0.z, f0.w + r0.w);
            float4 s1 = make_float4(f1.x + r1.x, f1.y + r1.y, f1.z + r1.z, f1.w + r1.w);
            *reinterpret_cast<float4*>(bp)     = s0;
            *reinterpret_cast<float4*>(bp + 4) = s1;
        }
        CP_WAIT1();
        __syncthreads();

        if (s + 2 < NS) {
            const int sb = (s + 2) % 3;
            const float* wp = w1 + (size_t)rowA * DD + (s + 2) * 16 + colA;
            cp16(sptr(As[sb] + rowA * ASTR + colA), wp);
            cp16(sptr(As[sb] + rowA * ASTR + colA + 4), wp + 4);
        }
        CP_COMMIT();

        {
            const int sn = (s + 1 < NS) ? s + 1 : s;
            const float* yf = g_Y + (size_t)(sn * 16 + kr) * NTOT + n0 + n8;
            const float* yb = yf + (size_t)DD * NTOT;
            f0 = *reinterpret_cast<const float4*>(yf);
            f1 = *reinterpret_cast<const float4*>(yf + 4);
            r0 = *reinterpret_cast<const float4*>(yb);
            r1 = *reinterpret_cast<const float4*>(yb + 4);
        }

        const float* A = As[s % 3];
        const float* B = Bs[s & 1];
#pragma unroll
        for (int kh = 0; kh < 16; kh += 8) {
            unsigned a[4][4], b[4][2];
#pragma unroll
            for (int mt = 0; mt < 4; mt++) {
                const int m = wm + mt * 16 + g;
                a[mt][0] = __float_as_uint(A[m * ASTR + kh + tig]);
                a[mt][1] = __float_as_uint(A[(m + 8) * ASTR + kh + tig]);
                a[mt][2] = __float_as_uint(A[m * ASTR + kh + tig + 4]);
                a[mt][3] = __float_as_uint(A[(m + 8) * ASTR + kh + tig + 4]);
            }
#pragma unroll
            for (int nt = 0; nt < 4; nt++) {
                const int n = wn + nt * 8 + g;
                b[nt][0] = __float_as_uint(B[(kh + tig) * EBSTR + n]);
                b[nt][1] = __float_as_uint(B[(kh + tig + 4) * EBSTR + n]);
            }
#pragma unroll
            for (int mt = 0; mt < 4; mt++)
#pragma unroll
                for (int nt = 0; nt < 4; nt++)
                    mma_tf32(c[mt][nt], a[mt], b[nt]);
        }
    }

    const int bb = blockIdx.x >> 2;
#pragma unroll
    for (int mt = 0; mt < 4; mt++) {
        const int jr = wm + mt * 16 + g;
        const float bv0 = b1v[jr];
        const float bv1 = b1v[jr + 8];
        float s0 = 0.f, s1 = 0.f;
#pragma unroll
        for (int nt = 0; nt < 4; nt++) {
            float e;
            e = c[mt][nt][0] + bv0; s0 += (e >= 0.f) ? e : 0.2f * e;
            e = c[mt][nt][1] + bv0; s0 += (e >= 0.f) ? e : 0.2f * e;
            e = c[mt][nt][2] + bv1; s1 += (e >= 0.f) ? e : 0.2f * e;
            e = c[mt][nt][3] + bv1; s1 += (e >= 0.f) ? e : 0.2f * e;
        }
        s0 += __shfl_xor_sync(0xffffffffu, s0, 1);
        s0 += __shfl_xor_sync(0xffffffffu, s0, 2);
        s1 += __shfl_xor_sync(0xffffffffu, s1, 1);
        s1 += __shfl_xor_sync(0xffffffffu, s1, 2);
        if (tig == 0) {
            atomicAdd(&g_M[bb * DD + jr], s0);
            atomicAdd(&g_M[bb * DD + jr + 8], s1);
        }
    }
}

// ============================================================================
// Kernel 4: out[b][i] = (1/T) * sum_j g_M[b][j] * emb_w2[i][j] + emb_b2[i]
// ============================================================================
__global__ __launch_bounds__(128) void out_kernel(const float* __restrict__ w2,
                                                  const float* __restrict__ b2,
                                                  float* __restrict__ out)
{
    __shared__ float m[128];
    const int b = blockIdx.x;
    const int i = threadIdx.x;
    m[i] = g_M[b * DD + i] * (1.f / (float)TT);
    __syncthreads();
    float s = b2[i];
    const float* wr = w2 + i * DD;
#pragma unroll 16
    for (int j = 0; j < DD; j++) s = fmaf(m[j], wr[j], s);
    out[b * DD + i] = s;
}

// ----------------------------------------------------------------------------
extern "C" void kernel_launch(void* const* d_in, const int* in_sizes, int n_in,
                              void* d_out, int out_size)
{
    const float* x      = (const float*)d_in[0];
    const float* fc1_w  = (const float*)d_in[1];
    const float* fc1_b  = (const float*)d_in[2];
    const float* wih_f  = (const float*)d_in[3];
    const float* whh_f  = (const float*)d_in[4];
    const float* bih_f  = (const float*)d_in[5];
    const float* bhh_f  = (const float*)d_in[6];
    const float* wih_b  = (const float*)d_in[7];
    const float* whh_b  = (const float*)d_in[8];
    const float* bih_b  = (const float*)d_in[9];
    const float* bhh_b  = (const float*)d_in[10];
    const float* lout_w = (const float*)d_in[11];
    const float* lout_b = (const float*)d_in[12];
    const float* emb_w1 = (const float*)d_in[13];
    const float* emb_b1 = (const float*)d_in[14];
    const float* emb_w2 = (const float*)d_in[15];
    const float* emb_b2 = (const float*)d_in[16];
    float* out = (float*)d_out;

    cudaFuncSetAttribute(fc1_bf16_kernel,
                         cudaFuncAttributeMaxDynamicSharedMemorySize, FC1_SMEM_B);
    cudaFuncSetAttribute(emb1_mma_kernel,
                         cudaFuncAttributeMaxDynamicSharedMemorySize, EMB_SMEM_B);

    prep_kernel<<<256, 256>>>(fc1_w);
    fc1_bf16_kernel<<<dim3(TT / 128, BB), 256, FC1_SMEM_B>>>(x, fc1_b);
    lstm_kernel<<<dim3(NTOT / 256, 2), 256>>>(wih_f, whh_f, bih_f, bhh_f,
                                              wih_b, whh_b, bih_b, bhh_b,
                                              lout_w, lout_b);
    emb1_mma_kernel<<<NTOT / 128, 256, EMB_SMEM_B>>>(emb_w1, emb_b1);
    out_kernel<<<BB, 128>>>(emb_w2, emb_b2, out);
}

// round 13
// speedup vs baseline: 2.3055x; 1.0468x over previous
#include <cuda_runtime.h>
#include <cstdint>

// Problem constants
#define BB   64
#define TT   512
#define NTOT 32768      // BB*TT
#define FF   1024
#define DD   128

// Scratch (device globals; no allocation allowed)
__device__ float g_G[DD * NTOT];        // fc1 output, layout [d][n]
__device__ unsigned g_Yfp[64 * NTOT];   // fwd Y: bf16x2 pairs (d even lo, d odd hi), [d2][n]
__device__ unsigned g_Ybp[64 * NTOT];   // bwd Y: same packing
__device__ float g_M[BB * DD];          // sum over t of lrelu(e1)
__device__ unsigned g_wb[DD * (FF/2)];  // fc1_w bf16x2, layout [m][k2]
__device__ unsigned g_w1hi[DD * 64];    // emb_w1 hi bf16x2, layout [j][k2]
__device__ unsigned g_w1lo[DD * 64];    // emb_w1 lo residual bf16x2

// ---------------------------------------------------------------- helpers
__device__ __forceinline__ float mtanh(float x) {
    float y;
    asm("tanh.approx.f32 %0, %1;" : "=f"(y) : "f"(x));
    return y;
}
__device__ __forceinline__ unsigned sptr(const void* p) {
    return (unsigned)__cvta_generic_to_shared(p);
}
__device__ __forceinline__ void cp16(unsigned dst, const void* src) {
    asm volatile("cp.async.cg.shared.global [%0], [%1], 16;" :: "r"(dst), "l"(src));
}
#define CP_COMMIT() asm volatile("cp.async.commit_group;")
#define CP_WAIT1()  asm volatile("cp.async.wait_group 1;")

__device__ __forceinline__ unsigned pack_bf2(float kodd, float keven) {
    unsigned d;
    asm("cvt.rn.bf16x2.f32 %0, %1, %2;" : "=r"(d) : "f"(kodd), "f"(keven));
    return d;
}
__device__ __forceinline__ float bf_lo_val(unsigned p) { return __uint_as_float(p << 16); }
__device__ __forceinline__ float bf_hi_val(unsigned p) { return __uint_as_float(p & 0xffff0000u); }
__device__ __forceinline__ unsigned hadd2(unsigned a, unsigned b) {
    unsigned d;
    asm("add.rn.bf16x2 %0, %1, %2;" : "=r"(d) : "r"(a), "r"(b));
    return d;
}
__device__ __forceinline__ void ldsm_x4(unsigned r[4], unsigned addr) {
    asm volatile("ldmatrix.sync.aligned.m8n8.x4.shared.b16 {%0,%1,%2,%3}, [%4];"
                 : "=r"(r[0]), "=r"(r[1]), "=r"(r[2]), "=r"(r[3]) : "r"(addr));
}
__device__ __forceinline__ void mma_bf16(float c[4], const unsigned a[4], const unsigned b[2]) {
    asm volatile(
        "mma.sync.aligned.m16n8k16.row.col.f32.bf16.bf16.f32 "
        "{%0,%1,%2,%3}, {%4,%5,%6,%7}, {%8,%9}, {%0,%1,%2,%3};"
        : "+f"(c[0]), "+f"(c[1]), "+f"(c[2]), "+f"(c[3])
        : "r"(a[0]), "r"(a[1]), "r"(a[2]), "r"(a[3]), "r"(b[0]), "r"(b[1]));
}

// ============================================================================
// Kernel 0: prep — fc1_w -> g_wb [m][k2]; emb_w1 -> hi/lo split [j][k2];
// zero g_M.
// ============================================================================
__global__ __launch_bounds__(256) void prep_kernel(const float* __restrict__ w,
                                                   const float* __restrict__ w1)
{
    const int idx = blockIdx.x * 256 + threadIdx.x;   // 0..65535
    {
        const int m  = idx >> 9;
        const int k2 = idx & 511;
        const float w0 = w[m * FF + 2 * k2];
        const float w1v = w[m * FF + 2 * k2 + 1];
        g_wb[m * 512 + k2] = pack_bf2(w1v, w0);
    }
    if (idx < DD * 64) {
        const int j  = idx >> 6;
        const int k2 = idx & 63;
        const float a0 = w1[j * DD + 2 * k2];
        const float a1 = w1[j * DD + 2 * k2 + 1];
        const unsigned hi = pack_bf2(a1, a0);
        const float l0 = a0 - bf_lo_val(hi);
        const float l1 = a1 - bf_hi_val(hi);
        g_w1hi[idx] = hi;
        g_w1lo[idx] = pack_bf2(l1, l0);
    }
    if (idx < BB * DD) g_M[idx] = 0.f;
}

// ============================================================================
// Kernel 1: fc1 GEMM, bf16 HMMA. CTA 128x128, BK=32, 8 warps 2x4, 2 CTAs/SM.
// A [m][k2] via cp.async + ldmatrix; B [k2][n] packed in-flight. (R12, proven)
// ============================================================================
#define AMST 20
#define BKST 136
#define FA_U (128 * AMST)
#define FB_U (16 * BKST)
#define FC1_SMEM_B ((3 * FA_U + 2 * FB_U) * 4)

__global__ __launch_bounds__(256, 2) void fc1_bf16_kernel(const float* __restrict__ x,
                                                          const float* __restrict__ bias)
{
    extern __shared__ __align__(16) unsigned smu[];
    unsigned* A_[3]; unsigned* B_[2];
#pragma unroll
    for (int i = 0; i < 3; i++) A_[i] = smu + i * FA_U;
#pragma unroll
    for (int i = 0; i < 2; i++) B_[i] = smu + 3 * FA_U + i * FB_U;

    const int tid  = threadIdx.x;
    const int lane = tid & 31;
    const int wid  = tid >> 5;
    const int g    = lane >> 2;
    const int tig  = lane & 3;
    const int wm   = (wid & 1) * 64;
    const int wn   = (wid >> 1) * 32;

    const int bt = blockIdx.y;
    const int t0 = blockIdx.x * 128;
    const float* xb = x + (size_t)bt * FF * TT;

    const int rowA  = tid >> 1;
    const int halfA = (tid & 1) * 8;
    const int kr = tid >> 4;
    const int q8 = (tid & 15) * 8;

    const unsigned lrow = wm + (lane & 7) + ((lane >> 3) & 1) * 8;
    const unsigned lak  = ((lane >> 4) & 1) * 4;

    float c[4][4][4];
#pragma unroll
    for (int i = 0; i < 4; i++)
#pragma unroll
        for (int j = 0; j < 4; j++)
#pragma unroll
            for (int k = 0; k < 4; k++) c[i][j][k] = 0.f;

    const int NS = FF / 32;

#pragma unroll
    for (int s = 0; s < 2; s++) {
        const unsigned* srcA = g_wb + rowA * 512 + s * 16 + halfA;
        unsigned dst = sptr(A_[s] + rowA * AMST + halfA);
        cp16(dst, srcA); cp16(dst + 16, srcA + 4);
        CP_COMMIT();
    }
    float4 u0, u1, v0, v1;
    {
        const float* xp = xb + (size_t)(2 * kr) * TT + t0 + q8;
        u0 = *reinterpret_cast<const float4*>(xp);
        u1 = *reinterpret_cast<const float4*>(xp + 4);
        v0 = *reinterpret_cast<const float4*>(xp + TT);
        v1 = *reinterpret_cast<const float4*>(xp + TT + 4);
    }

    for (int s = 0; s < NS; s++) {
        {
            unsigned* bp = B_[s & 1] + kr * BKST + q8;
            const float ue[8] = {u0.x, u0.y, u0.z, u0.w, u1.x, u1.y, u1.z, u1.w};
            const float vo[8] = {v0.x, v0.y, v0.z, v0.w, v1.x, v1.y, v1.z, v1.w};
            unsigned h[8];
#pragma unroll
            for (int i = 0; i < 8; i++) h[i] = pack_bf2(vo[i], ue[i]);
            *reinterpret_cast<uint4*>(bp)     = make_uint4(h[0], h[1], h[2], h[3]);
            *reinterpret_cast<uint4*>(bp + 4) = make_uint4(h[4], h[5], h[6], h[7]);
        }
        CP_WAIT1();
        __syncthreads();

        if (s + 2 < NS) {
            const unsigned* srcA = g_wb + rowA * 512 + (s + 2) * 16 + halfA;
            unsigned dst = sptr(A_[(s + 2) % 3] + rowA * AMST + halfA);
            cp16(dst, srcA); cp16(dst + 16, srcA + 4);
        }
        CP_COMMIT();

        {
            const int sn = (s + 1 < NS) ? s + 1 : s;
            const float* xp = xb + (size_t)(sn * 32 + 2 * kr) * TT + t0 + q8;
            u0 = *reinterpret_cast<const float4*>(xp);
            u1 = *reinterpret_cast<const float4*>(xp + 4);
            v0 = *reinterpret_cast<const float4*>(xp + TT);
            v1 = *reinterpret_cast<const float4*>(xp + TT + 4);
        }

        const unsigned Abase = sptr(A_[s % 3]);
        const unsigned* B = B_[s & 1];
#pragma unroll
        for (int g16 = 0; g16 < 2; g16++) {
            unsigned a[4][4], b[4][2];
#pragma unroll
            for (int mt = 0; mt < 4; mt++) {
                const unsigned ad = Abase + ((lrow + mt * 16) * AMST + g16 * 8 + lak) * 4;
                ldsm_x4(a[mt], ad);
            }
#pragma unroll
            for (int nt = 0; nt < 4; nt++) {
                const int n = wn + nt * 8 + g;
                b[nt][0] = B[(g16 * 8 + tig) * BKST + n];
                b[nt][1] = B[(g16 * 8 + tig + 4) * BKST + n];
            }
#pragma unroll
            for (int mt = 0; mt < 4; mt++)
#pragma unroll
                for (int nt = 0; nt < 4; nt++)
                    mma_bf16(c[mt][nt], a[mt], b[nt]);
        }
    }

    const int nbase = bt * TT + t0 + wn;
#pragma unroll
    for (int mt = 0; mt < 4; mt++) {
        const int dr = wm + mt * 16 + g;
        const float bv0 = bias[dr];
        const float bv1 = bias[dr + 8];
#pragma unroll
        for (int nt = 0; nt < 4; nt++) {
            const int ncol = nbase + nt * 8 + 2 * tig;
            float2 w0 = make_float2(c[mt][nt][0] + bv0, c[mt][nt][1] + bv0);
            float2 w1 = make_float2(c[mt][nt][2] + bv1, c[mt][nt][3] + bv1);
            *reinterpret_cast<float2*>(g_G + (size_t)dr * NTOT + ncol) = w0;
            *reinterpret_cast<float2*>(g_G + (size_t)(dr + 8) * NTOT + ncol) = w1;
        }
    }
}

// ============================================================================
// Kernel 2: LSTM, 1 seq/thread, pointer-walk, PF=8 prefetch ring. Emits Y as
// bf16x2 d-pairs: fwd -> g_Yfp, bwd -> g_Ybp (one STG.32 per 2 steps).
// ============================================================================
#define PF 8

__global__ __launch_bounds__(256) void lstm_kernel(
    const float* __restrict__ wih_f, const float* __restrict__ whh_f,
    const float* __restrict__ bih_f, const float* __restrict__ bhh_f,
    const float* __restrict__ wih_b, const float* __restrict__ whh_b,
    const float* __restrict__ bih_b, const float* __restrict__ bhh_b,
    const float* __restrict__ lout_w, const float* __restrict__ lout_b)
{
    const int n   = blockIdx.x * 256 + threadIdx.x;
    const int dir = blockIdx.y;

    const float* wih = dir ? wih_b : wih_f;
    const float* whh = dir ? whh_b : whh_f;
    const float* bih = dir ? bih_b : bih_f;
    const float* bhh = dir ? bhh_b : bhh_f;

    const float wi0 = 0.5f * wih[0], wh0 = 0.5f * whh[0], b0 = 0.5f * (bih[0] + bhh[0]);
    const float wi1 = 0.5f * wih[1], wh1 = 0.5f * whh[1], b1 = 0.5f * (bih[1] + bhh[1]);
    const float wi2 =        wih[2], wh2 =        whh[2], b2 =        (bih[2] + bhh[2]);
    const float wi3 = 0.5f * wih[3], wh3 = 0.5f * whh[3], b3 = 0.5f * (bih[3] + bhh[3]);

    const float lw = dir ? lout_w[1] : lout_w[0];
    const float lb = dir ? 0.f : lout_b[0];

    const int d0 = dir ? DD - 1 : 0;
    const long stp = dir ? -(long)NTOT : (long)NTOT;

    const float* pf = g_G + (size_t)d0 * NTOT + n;
    unsigned* gy = dir ? (g_Ybp + (size_t)63 * NTOT + n) : (g_Yfp + n);

    float h = 0.f, c = 0.f, yprev = 0.f;

    float q[PF];
#pragma unroll
    for (int p = 0; p < PF; p++) { q[p] = *pf; pf += stp; }

#pragma unroll 8
    for (int it = 0; it < DD; it++) {
        const float xv = q[it % PF];
        if (it + PF < DD) { q[it % PF] = *pf; pf += stp; }

        const float ai = fmaf(wi0, xv, fmaf(wh0, h, b0));
        const float af = fmaf(wi1, xv, fmaf(wh1, h, b1));
        const float ag = fmaf(wi2, xv, fmaf(wh2, h, b2));
        const float ao = fmaf(wi3, xv, fmaf(wh3, h, b3));

        const float si = fmaf(0.5f, mtanh(ai), 0.5f);
        const float sf = fmaf(0.5f, mtanh(af), 0.5f);
        const float tg = mtanh(ag);
        const float so = fmaf(0.5f, mtanh(ao), 0.5f);

        c = fmaf(sf, c, si * tg);
        h = so * mtanh(c);

        const float y = fmaf(lw, h, lb);
        if (it & 1) {
            // fwd: pair (keven = yprev at even d, kodd = y at odd d)
            // bwd: d even now => keven = y, kodd = yprev (d+1)
            *gy = dir ? pack_bf2(yprev, y) : pack_bf2(y, yprev);
            gy += stp;
        } else {
            yprev = y;
        }
    }
}

// ============================================================================
// Kernel 3: emb1 — e1 = w1 @ (Yf+Yb) + b1, w1 in hi/lo bf16 split (2-term),
// Y summed in bf16x2 (pairs already along d). lrelu + t-sum -> atomicAdd g_M.
// CTA 128(j) x 128(n), BK=32 (16 k2-rows/stage), NS=4, 2 CTAs/SM.
// A via cp.async + ldmatrix (hi & lo); B via hadd2 of pair-words.
// ============================================================================
#define EA_ST 20                       // A smem m-row stride (uints)
#define EB_ST 136                      // B smem k2-row stride (uints)
#define E_A_U (128 * EA_ST)            // per A array per stage
#define E_B_U (16 * EB_ST)
#define EMB_SMEM_B ((3 * 2 * E_A_U + 2 * E_B_U) * 4)

__global__ __launch_bounds__(256, 2) void emb1_bf16_kernel(const float* __restrict__ b1v)
{
    extern __shared__ __align__(16) unsigned smu[];
    unsigned* AH_[3]; unsigned* AL_[3]; unsigned* B_[2];
#pragma unroll
    for (int i = 0; i < 3; i++) {
        AH_[i] = smu + (2 * i) * E_A_U;
        AL_[i] = smu + (2 * i + 1) * E_A_U;
    }
#pragma unroll
    for (int i = 0; i < 2; i++) B_[i] = smu + 6 * E_A_U + i * E_B_U;

    const int tid  = threadIdx.x;
    const int lane = tid & 31;
    const int wid  = tid >> 5;
    const int g    = lane >> 2;
    const int tig  = lane & 3;
    const int wm   = (wid & 1) * 64;
    const int wn   = (wid >> 1) * 32;

    const int n0 = blockIdx.x * 128;

    const int rowA  = tid >> 1;
    const int halfA = (tid & 1) * 8;
    const int kr = tid >> 4;          // 0..15
    const int q8 = (tid & 15) * 8;    // 0..120

    const unsigned lrow = wm + (lane & 7) + ((lane >> 3) & 1) * 8;
    const unsigned lak  = ((lane >> 4) & 1) * 4;

    float c[4][4][4];
#pragma unroll
    for (int i = 0; i < 4; i++)
#pragma unroll
        for (int j = 0; j < 4; j++)
#pragma unroll
            for (int k = 0; k < 4; k++) c[i][j][k] = 0.f;

    const int NS = 4;   // K = 128, BK = 32

    // prologue: A stages 0,1; B stage 0 into registers
#pragma unroll
    for (int s = 0; s < 2; s++) {
        const unsigned* sh = g_w1hi + rowA * 64 + s * 16 + halfA;
        const unsigned* sl = g_w1lo + rowA * 64 + s * 16 + halfA;
        unsigned dh = sptr(AH_[s] + rowA * EA_ST + halfA);
        unsigned dl = sptr(AL_[s] + rowA * EA_ST + halfA);
        cp16(dh, sh); cp16(dh + 16, sh + 4);
        cp16(dl, sl); cp16(dl + 16, sl + 4);
        CP_COMMIT();
    }
    uint4 f0, f1, r0, r1;
    {
        const unsigned* yf = g_Yfp + (size_t)kr * NTOT + n0 + q8;
        const unsigned* yb = g_Ybp + (size_t)kr * NTOT + n0 + q8;
        f0 = *reinterpret_cast<const uint4*>(yf);
        f1 = *reinterpret_cast<const uint4*>(yf + 4);
        r0 = *reinterpret_cast<const uint4*>(yb);
        r1 = *reinterpret_cast<const uint4*>(yb + 4);
    }

    for (int s = 0; s < NS; s++) {
        // B(s): sum fwd+bwd pair-words, store
        {
            unsigned* bp = B_[s & 1] + kr * EB_ST + q8;
            uint4 s0 = make_uint4(hadd2(f0.x, r0.x), hadd2(f0.y, r0.y),
                                  hadd2(f0.z, r0.z), hadd2(f0.w, r0.w));
            uint4 s1 = make_uint4(hadd2(f1.x, r1.x), hadd2(f1.y, r1.y),
                                  hadd2(f1.z, r1.z), hadd2(f1.w, r1.w));
            *reinterpret_cast<uint4*>(bp)     = s0;
            *reinterpret_cast<uint4*>(bp + 4) = s1;
        }
        CP_WAIT1();
        __syncthreads();

        if (s + 2 < NS) {
            const unsigned* sh = g_w1hi + rowA * 64 + (s + 2) * 16 + halfA;
            const unsigned* sl = g_w1lo + rowA * 64 + (s + 2) * 16 + halfA;
            unsigned dh = sptr(AH_[(s + 2) % 3] + rowA * EA_ST + halfA);
            unsigned dl = sptr(AL_[(s + 2) % 3] + rowA * EA_ST + halfA);
            cp16(dh, sh); cp16(dh + 16, sh + 4);
            cp16(dl, sl); cp16(dl + 16, sl + 4);
        }
        CP_COMMIT();

        // prefetch B(s+1) pair-words
        {
            const int sn = (s + 1 < NS) ? s + 1 : s;
            const unsigned* yf = g_Yfp + (size_t)(sn * 16 + kr) * NTOT + n0 + q8;
            const unsigned* yb = g_Ybp + (size_t)(sn * 16 + kr) * NTOT + n0 + q8;
            f0 = *reinterpret_cast<const uint4*>(yf);
            f1 = *reinterpret_cast<const uint4*>(yf + 4);
            r0 = *reinterpret_cast<const uint4*>(yb);
            r1 = *reinterpret_cast<const uint4*>(yb + 4);
        }

        const unsigned AHb = sptr(AH_[s % 3]);
        const unsigned ALb = sptr(AL_[s % 3]);
        const unsigned* B = B_[s & 1];
#pragma unroll
        for (int g16 = 0; g16 < 2; g16++) {
            unsigned ah[4][4], al[4][4], b[4][2];
#pragma unroll
            for (int mt = 0; mt < 4; mt++) {
                const unsigned off = ((lrow + mt * 16) * EA_ST + g16 * 8 + lak) * 4;
                ldsm_x4(ah[mt], AHb + off);
                ldsm_x4(al[mt], ALb + off);
            }
#pragma unroll
            for (int nt = 0; nt < 4; nt++) {
                const int n = wn + nt * 8 + g;
                b[nt][0] = B[(g16 * 8 + tig) * EB_ST + n];
                b[nt][1] = B[(g16 * 8 + tig + 4) * EB_ST + n];
            }
#pragma unroll
            for (int mt = 0; mt < 4; mt++)
#pragma unroll
                for (int nt = 0; nt < 4; nt++) {
                    mma_bf16(c[mt][nt], ah[mt], b[nt]);
                    mma_bf16(c[mt][nt], al[mt], b[nt]);
                }
        }
    }

    // epilogue: bias + leaky-relu + sum over n, quad-reduce, atomicAdd
    const int bb = blockIdx.x >> 2;   // 4 n-tiles of 128 per batch
#pragma unroll
    for (int mt = 0; mt < 4; mt++) {
        const int jr = wm + mt * 16 + g;
        const float bv0 = b1v[jr];
        const float bv1 = b1v[jr + 8];
        float s0 = 0.f, s1 = 0.f;
#pragma unroll
        for (int nt = 0; nt < 4; nt++) {
            float e;
            e = c[mt][nt][0] + bv0; s0 += (e >= 0.f) ? e : 0.2f * e;
            e = c[mt][nt][1] + bv0; s0 += (e >= 0.f) ? e : 0.2f * e;
            e = c[mt][nt][2] + bv1; s1 += (e >= 0.f) ? e : 0.2f * e;
            e = c[mt][nt][3] + bv1; s1 += (e >= 0.f) ? e : 0.2f * e;
        }
        s0 += __shfl_xor_sync(0xffffffffu, s0, 1);
        s0 += __shfl_xor_sync(0xffffffffu, s0, 2);
        s1 += __shfl_xor_sync(0xffffffffu, s1, 1);
        s1 += __shfl_xor_sync(0xffffffffu, s1, 2);
        if (tig == 0) {
            atomicAdd(&g_M[bb * DD + jr], s0);
            atomicAdd(&g_M[bb * DD + jr + 8], s1);
        }
    }
}

// ============================================================================
// Kernel 4: out[b][i] = (1/T) * sum_j g_M[b][j] * emb_w2[i][j] + emb_b2[i]
// ============================================================================
__global__ __launch_bounds__(128) void out_kernel(const float* __restrict__ w2,
                                                  const float* __restrict__ b2,
                                                  float* __restrict__ out)
{
    __shared__ float m[128];
    const int b = blockIdx.x;
    const int i = threadIdx.x;
    m[i] = g_M[b * DD + i] * (1.f / (float)TT);
    __syncthreads();
    float s = b2[i];
    const float* wr = w2 + i * DD;
#pragma unroll 16
    for (int j = 0; j < DD; j++) s = fmaf(m[j], wr[j], s);
    out[b * DD + i] = s;
}

// ----------------------------------------------------------------------------
extern "C" void kernel_launch(void* const* d_in, const int* in_sizes, int n_in,
                              void* d_out, int out_size)
{
    const float* x      = (const float*)d_in[0];
    const float* fc1_w  = (const float*)d_in[1];
    const float* fc1_b  = (const float*)d_in[2];
    const float* wih_f  = (const float*)d_in[3];
    const float* whh_f  = (const float*)d_in[4];
    const float* bih_f  = (const float*)d_in[5];
    const float* bhh_f  = (const float*)d_in[6];
    const float* wih_b  = (const float*)d_in[7];
    const float* whh_b  = (const float*)d_in[8];
    const float* bih_b  = (const float*)d_in[9];
    const float* bhh_b  = (const float*)d_in[10];
    const float* lout_w = (const float*)d_in[11];
    const float* lout_b = (const float*)d_in[12];
    const float* emb_w1 = (const float*)d_in[13];
    const float* emb_b1 = (const float*)d_in[14];
    const float* emb_w2 = (const float*)d_in[15];
    const float* emb_b2 = (const float*)d_in[16];
    float* out = (float*)d_out;

    cudaFuncSetAttribute(fc1_bf16_kernel,
                         cudaFuncAttributeMaxDynamicSharedMemorySize, FC1_SMEM_B);
    cudaFuncSetAttribute(emb1_bf16_kernel,
                         cudaFuncAttributeMaxDynamicSharedMemorySize, EMB_SMEM_B);

    prep_kernel<<<256, 256>>>(fc1_w, emb_w1);
    fc1_bf16_kernel<<<dim3(TT / 128, BB), 256, FC1_SMEM_B>>>(x, fc1_b);
    lstm_kernel<<<dim3(NTOT / 256, 2), 256>>>(wih_f, whh_f, bih_f, bhh_f,
                                              wih_b, whh_b, bih_b, bhh_b,
                                              lout_w, lout_b);
    emb1_bf16_kernel<<<NTOT / 128, 256, EMB_SMEM_B>>>(emb_b1);
    out_kernel<<<BB, 128>>>(emb_w2, emb_b2, out);
}

// round 14
// speedup vs baseline: 2.6969x; 1.1698x over previous
#include <cuda_runtime.h>
#include <cstdint>

// Problem constants
#define BB   64
#define TT   512
#define NTOT 32768      // BB*TT
#define FF   1024
#define DD   128

// Scratch (device globals; no allocation allowed)
__device__ float g_G[DD * NTOT];        // fc1 output, layout [d][n] (L2-resident hand-off)
__device__ float g_M[BB * DD];          // sum over t of lrelu(e1)
__device__ unsigned g_wb[DD * (FF/2)];  // fc1_w bf16x2, layout [m][k2]
__device__ unsigned g_w1hi[DD * 64];    // emb_w1 hi bf16x2, layout [j][k2]
__device__ unsigned g_w1lo[DD * 64];    // emb_w1 lo residual bf16x2

// ---------------------------------------------------------------- helpers
__device__ __forceinline__ float mtanh(float x) {
    float y;
    asm("tanh.approx.f32 %0, %1;" : "=f"(y) : "f"(x));
    return y;
}
__device__ __forceinline__ unsigned sptr(const void* p) {
    return (unsigned)__cvta_generic_to_shared(p);
}
__device__ __forceinline__ void cp16(unsigned dst, const void* src) {
    asm volatile("cp.async.cg.shared.global [%0], [%1], 16;" :: "r"(dst), "l"(src));
}
#define CP_COMMIT() asm volatile("cp.async.commit_group;")
#define CP_WAIT0()  asm volatile("cp.async.wait_group 0;")

__device__ __forceinline__ unsigned pack_bf2(float kodd, float keven) {
    unsigned d;
    asm("cvt.rn.bf16x2.f32 %0, %1, %2;" : "=r"(d) : "f"(kodd), "f"(keven));
    return d;
}
__device__ __forceinline__ float bf_lo_val(unsigned p) { return __uint_as_float(p << 16); }
__device__ __forceinline__ float bf_hi_val(unsigned p) { return __uint_as_float(p & 0xffff0000u); }
__device__ __forceinline__ unsigned hadd2(unsigned a, unsigned b) {
    unsigned d;
    asm("add.rn.bf16x2 %0, %1, %2;" : "=r"(d) : "r"(a), "r"(b));
    return d;
}
__device__ __forceinline__ void ldsm_x4(unsigned r[4], unsigned addr) {
    asm volatile("ldmatrix.sync.aligned.m8n8.x4.shared.b16 {%0,%1,%2,%3}, [%4];"
                 : "=r"(r[0]), "=r"(r[1]), "=r"(r[2]), "=r"(r[3]) : "r"(addr));
}
__device__ __forceinline__ void mma_bf16(float c[4], const unsigned a[4], const unsigned b[2]) {
    asm volatile(
        "mma.sync.aligned.m16n8k16.row.col.f32.bf16.bf16.f32 "
        "{%0,%1,%2,%3}, {%4,%5,%6,%7}, {%8,%9}, {%0,%1,%2,%3};"
        : "+f"(c[0]), "+f"(c[1]), "+f"(c[2]), "+f"(c[3])
        : "r"(a[0]), "r"(a[1]), "r"(a[2]), "r"(a[3]), "r"(b[0]), "r"(b[1]));
}

// ============================================================================
// Kernel 0: prep — fc1_w -> g_wb [m][k2]; emb_w1 -> hi/lo split; zero g_M.
// ============================================================================
__global__ __launch_bounds__(256) void prep_kernel(const float* __restrict__ w,
                                                   const float* __restrict__ w1)
{
    const int idx = blockIdx.x * 256 + threadIdx.x;   // 0..65535
    {
        const int m  = idx >> 9;
        const int k2 = idx & 511;
        const float w0 = w[m * FF + 2 * k2];
        const float w1v = w[m * FF + 2 * k2 + 1];
        g_wb[m * 512 + k2] = pack_bf2(w1v, w0);
    }
    if (idx < DD * 64) {
        const int j  = idx >> 6;
        const int k2 = idx & 63;
        const float a0 = w1[j * DD + 2 * k2];
        const float a1 = w1[j * DD + 2 * k2 + 1];
        const unsigned hi = pack_bf2(a1, a0);
        const float l0 = a0 - bf_lo_val(hi);
        const float l1 = a1 - bf_hi_val(hi);
        g_w1hi[idx] = hi;
        g_w1lo[idx] = pack_bf2(l1, l0);
    }
    if (idx < BB * DD) g_M[idx] = 0.f;
}

// ============================================================================
// MEGAKERNEL: fc1 (bf16 HMMA) -> bi-LSTM -> emb1 (bf16 split HMMA), fused.
// CTA = one (batch bt, 128-wide t-tile): computes G[128d][128t], runs the
// LSTM for its 128 sequences (G round-trips through L2 only), keeps Y pairs
// in smem, and accumulates the lrelu(e1) t-sum into g_M.
// ============================================================================
#define P1A_U 2560                 // 128 rows x 20 (phase-1 A stage)
#define P1B_U 2176                 // 16 rows x 136 (phase-1 B stage)
#define RING_U (2*P1A_U + 2*P1B_U) // 9472 uints (phase-3 reuses: 4x1536=6144)
#define P3A_U 1536                 // 128 rows x 12 (phase-3 A stage)
#define SY_ST 136
#define SY_U  (64 * SY_ST)         // 8704 uints per Y buffer
#define MEGA_U (RING_U + 2 * SY_U) // 26880 uints
#define MEGA_B (MEGA_U * 4)        // 107520 bytes
#define PF 8

__global__ __launch_bounds__(256, 2) void mega_kernel(
    const float* __restrict__ x,    const float* __restrict__ fc1_b,
    const float* __restrict__ wih_f, const float* __restrict__ whh_f,
    const float* __restrict__ bih_f, const float* __restrict__ bhh_f,
    const float* __restrict__ wih_b, const float* __restrict__ whh_b,
    const float* __restrict__ bih_b, const float* __restrict__ bhh_b,
    const float* __restrict__ lout_w, const float* __restrict__ lout_b,
    const float* __restrict__ b1v)
{
    extern __shared__ __align__(16) unsigned smu[];
    unsigned* A_[2]; unsigned* B_[2];
    A_[0] = smu;             A_[1] = smu + P1A_U;
    B_[0] = smu + 2 * P1A_U; B_[1] = smu + 2 * P1A_U + P1B_U;
    unsigned* sYf = smu + RING_U;
    unsigned* sYb = smu + RING_U + SY_U;

    const int tid  = threadIdx.x;
    const int lane = tid & 31;
    const int wid  = tid >> 5;
    const int g    = lane >> 2;
    const int tig  = lane & 3;
    const int wm   = (wid & 1) * 64;
    const int wn   = (wid >> 1) * 32;

    const int bt = blockIdx.y;
    const int t0 = blockIdx.x * 128;
    const float* xb = x + (size_t)bt * FF * TT;

    const int rowA  = tid >> 1;
    const int halfA = (tid & 1) * 8;
    const int kr = tid >> 4;
    const int q8 = (tid & 15) * 8;

    const unsigned lrow = wm + (lane & 7) + ((lane >> 3) & 1) * 8;
    const unsigned lak  = ((lane >> 4) & 1) * 4;

    float c[4][4][4];
#pragma unroll
    for (int i = 0; i < 4; i++)
#pragma unroll
        for (int j = 0; j < 4; j++)
#pragma unroll
            for (int k = 0; k < 4; k++) c[i][j][k] = 0.f;

    // ======================= Phase 1: fc1 GEMM =======================
    {
        const int NS = FF / 32;   // 32 stages

        // prologue: A(0)
        {
            const unsigned* srcA = g_wb + rowA * 512 + halfA;
            unsigned dst = sptr(A_[0] + rowA * 20 + halfA);
            cp16(dst, srcA); cp16(dst + 16, srcA + 4);
            CP_COMMIT();
        }
        float4 u0, u1, v0, v1;
        {
            const float* xp = xb + (size_t)(2 * kr) * TT + t0 + q8;
            u0 = *reinterpret_cast<const float4*>(xp);
            u1 = *reinterpret_cast<const float4*>(xp + 4);
            v0 = *reinterpret_cast<const float4*>(xp + TT);
            v1 = *reinterpret_cast<const float4*>(xp + TT + 4);
        }

        for (int s = 0; s < NS; s++) {
            // pack + store B(s)
            {
                unsigned* bp = B_[s & 1] + kr * 136 + q8;
                const float ue[8] = {u0.x, u0.y, u0.z, u0.w, u1.x, u1.y, u1.z, u1.w};
                const float vo[8] = {v0.x, v0.y, v0.z, v0.w, v1.x, v1.y, v1.z, v1.w};
                unsigned h[8];
#pragma unroll
                for (int i = 0; i < 8; i++) h[i] = pack_bf2(vo[i], ue[i]);
                *reinterpret_cast<uint4*>(bp)     = make_uint4(h[0], h[1], h[2], h[3]);
                *reinterpret_cast<uint4*>(bp + 4) = make_uint4(h[4], h[5], h[6], h[7]);
            }
            CP_WAIT0();          // A(s) landed
            __syncthreads();     // B(s) visible; buffer (s+1)&1 free

            if (s + 1 < NS) {
                const unsigned* srcA = g_wb + rowA * 512 + (s + 1) * 16 + halfA;
                unsigned dst = sptr(A_[(s + 1) & 1] + rowA * 20 + halfA);
                cp16(dst, srcA); cp16(dst + 16, srcA + 4);
            }
            CP_COMMIT();

            // prefetch B(s+1)
            {
                const int sn = (s + 1 < NS) ? s + 1 : s;
                const float* xp = xb + (size_t)(sn * 32 + 2 * kr) * TT + t0 + q8;
                u0 = *reinterpret_cast<const float4*>(xp);
                u1 = *reinterpret_cast<const float4*>(xp + 4);
                v0 = *reinterpret_cast<const float4*>(xp + TT);
                v1 = *reinterpret_cast<const float4*>(xp + TT + 4);
            }

            const unsigned Abase = sptr(A_[s & 1]);
            const unsigned* B = B_[s & 1];
#pragma unroll
            for (int g16 = 0; g16 < 2; g16++) {
                unsigned a[4][4], b[4][2];
#pragma unroll
                for (int mt = 0; mt < 4; mt++) {
                    const unsigned ad = Abase + ((lrow + mt * 16) * 20 + g16 * 8 + lak) * 4;
                    ldsm_x4(a[mt], ad);
                }
#pragma unroll
                for (int nt = 0; nt < 4; nt++) {
                    const int n = wn + nt * 8 + g;
                    b[nt][0] = B[(g16 * 8 + tig) * 136 + n];
                    b[nt][1] = B[(g16 * 8 + tig + 4) * 136 + n];
                }
#pragma unroll
                for (int mt = 0; mt < 4; mt++)
#pragma unroll
                    for (int nt = 0; nt < 4; nt++)
                        mma_bf16(c[mt][nt], a[mt], b[nt]);
            }
        }

        // epilogue: add bias, store G tile to global (L2-resident hand-off)
        const int nbase = bt * TT + t0 + wn;
#pragma unroll
        for (int mt = 0; mt < 4; mt++) {
            const int dr = wm + mt * 16 + g;
            const float bv0 = fc1_b[dr];
            const float bv1 = fc1_b[dr + 8];
#pragma unroll
            for (int nt = 0; nt < 4; nt++) {
                const int ncol = nbase + nt * 8 + 2 * tig;
                float2 w0 = make_float2(c[mt][nt][0] + bv0, c[mt][nt][1] + bv0);
                float2 w1 = make_float2(c[mt][nt][2] + bv1, c[mt][nt][3] + bv1);
                *reinterpret_cast<float2*>(g_G + (size_t)dr * NTOT + ncol) = w0;
                *reinterpret_cast<float2*>(g_G + (size_t)(dr + 8) * NTOT + ncol) = w1;
            }
        }
        CP_WAIT0();
    }
    __syncthreads();   // G visible CTA-wide

    // ======================= Phase 2: bi-LSTM =======================
    {
        const int dir = tid >> 7;          // 0 fwd, 1 bwd
        const int nl  = tid & 127;
        const int n   = bt * TT + t0 + nl;

        const float* wih = dir ? wih_b : wih_f;
        const float* whh = dir ? whh_b : whh_f;
        const float* bih = dir ? bih_b : bih_f;
        const float* bhh = dir ? bhh_b : bhh_f;

        const float wi0 = 0.5f * wih[0], wh0 = 0.5f * whh[0], b0 = 0.5f * (bih[0] + bhh[0]);
        const float wi1 = 0.5f * wih[1], wh1 = 0.5f * whh[1], b1 = 0.5f * (bih[1] + bhh[1]);
        const float wi2 =        wih[2], wh2 =        whh[2], b2 =        (bih[2] + bhh[2]);
        const float wi3 = 0.5f * wih[3], wh3 = 0.5f * whh[3], b3 = 0.5f * (bih[3] + bhh[3]);

        const float lw = dir ? lout_w[1] : lout_w[0];
        const float lb = dir ? 0.f : lout_b[0];

        const int d0 = dir ? DD - 1 : 0;
        const long stp = dir ? -(long)NTOT : (long)NTOT;
        const float* pf = g_G + (size_t)d0 * NTOT + n;
        unsigned* yw = (dir ? (sYb + 63 * SY_ST) : sYf) + nl;
        const int yst = dir ? -SY_ST : SY_ST;

        float h = 0.f, cc = 0.f, yprev = 0.f;

        float q[PF];
#pragma unroll
        for (int p = 0; p < PF; p++) { q[p] = *pf; pf += stp; }

#pragma unroll 8
        for (int it = 0; it < DD; it++) {
            const float xv = q[it % PF];
            if (it + PF < DD) { q[it % PF] = *pf; pf += stp; }

            const float ai = fmaf(wi0, xv, fmaf(wh0, h, b0));
            const float af = fmaf(wi1, xv, fmaf(wh1, h, b1));
            const float ag = fmaf(wi2, xv, fmaf(wh2, h, b2));
            const float ao = fmaf(wi3, xv, fmaf(wh3, h, b3));

            const float si = fmaf(0.5f, mtanh(ai), 0.5f);
            const float sf = fmaf(0.5f, mtanh(af), 0.5f);
            const float tg = mtanh(ag);
            const float so = fmaf(0.5f, mtanh(ao), 0.5f);

            cc = fmaf(sf, cc, si * tg);
            h = so * mtanh(cc);

            const float y = fmaf(lw, h, lb);
            if (it & 1) {
                *yw = dir ? pack_bf2(yprev, y) : pack_bf2(y, yprev);
                yw += yst;
            } else {
                yprev = y;
            }
        }
    }
    __syncthreads();   // sYf / sYb ready

    // ======================= Phase 3: emb1 =======================
    {
        unsigned* AH_[2]; unsigned* AL_[2];
        AH_[0] = smu;             AH_[1] = smu + P3A_U;
        AL_[0] = smu + 2 * P3A_U; AL_[1] = smu + 3 * P3A_U;

        const int rowW  = tid >> 1;
        const int halfW = (tid & 1) * 4;

#pragma unroll
        for (int i = 0; i < 4; i++)
#pragma unroll
            for (int j = 0; j < 4; j++)
#pragma unroll
                for (int k = 0; k < 4; k++) c[i][j][k] = 0.f;

        // prologue: stage 0
        cp16(sptr(AH_[0] + rowW * 12 + halfW), g_w1hi + rowW * 64 + halfW);
        cp16(sptr(AL_[0] + rowW * 12 + halfW), g_w1lo + rowW * 64 + halfW);
        CP_COMMIT();

        for (int s = 0; s < 8; s++) {        // 8 stages of 8 k2-rows (k16 each)
            CP_WAIT0();          // A(s) landed
            __syncthreads();     // all warps past MMA(s-1): buffer (s+1)&1 free

            if (s + 1 < 8) {
                cp16(sptr(AH_[(s + 1) & 1] + rowW * 12 + halfW),
                     g_w1hi + rowW * 64 + (s + 1) * 8 + halfW);
                cp16(sptr(AL_[(s + 1) & 1] + rowW * 12 + halfW),
                     g_w1lo + rowW * 64 + (s + 1) * 8 + halfW);
            }
            CP_COMMIT();

            const unsigned AHb = sptr(AH_[s & 1]);
            const unsigned ALb = sptr(AL_[s & 1]);

            unsigned ah[4][4], al[4][4], b[4][2];
#pragma unroll
            for (int mt = 0; mt < 4; mt++) {
                const unsigned off = ((lrow + mt * 16) * 12 + lak) * 4;
                ldsm_x4(ah[mt], AHb + off);
                ldsm_x4(al[mt], ALb + off);
            }
#pragma unroll
            for (int nt = 0; nt < 4; nt++) {
                const int n = wn + nt * 8 + g;
                b[nt][0] = hadd2(sYf[(s * 8 + tig) * SY_ST + n],
                                 sYb[(s * 8 + tig) * SY_ST + n]);
                b[nt][1] = hadd2(sYf[(s * 8 + tig + 4) * SY_ST + n],
                                 sYb[(s * 8 + tig + 4) * SY_ST + n]);
            }
#pragma unroll
            for (int mt = 0; mt < 4; mt++)
#pragma unroll
                for (int nt = 0; nt < 4; nt++) {
                    mma_bf16(c[mt][nt], ah[mt], b[nt]);
                    mma_bf16(c[mt][nt], al[mt], b[nt]);
                }
        }

        // epilogue: bias + leaky-relu + sum over n, quad-reduce, atomicAdd
#pragma unroll
        for (int mt = 0; mt < 4; mt++) {
            const int jr = wm + mt * 16 + g;
            const float bv0 = b1v[jr];
            const float bv1 = b1v[jr + 8];
            float s0 = 0.f, s1 = 0.f;
#pragma unroll
            for (int nt = 0; nt < 4; nt++) {
                float e;
                e = c[mt][nt][0] + bv0; s0 += (e >= 0.f) ? e : 0.2f * e;
                e = c[mt][nt][1] + bv0; s0 += (e >= 0.f) ? e : 0.2f * e;
                e = c[mt][nt][2] + bv1; s1 += (e >= 0.f) ? e : 0.2f * e;
                e = c[mt][nt][3] + bv1; s1 += (e >= 0.f) ? e : 0.2f * e;
            }
            s0 += __shfl_xor_sync(0xffffffffu, s0, 1);
            s0 += __shfl_xor_sync(0xffffffffu, s0, 2);
            s1 += __shfl_xor_sync(0xffffffffu, s1, 1);
            s1 += __shfl_xor_sync(0xffffffffu, s1, 2);
            if (tig == 0) {
                atomicAdd(&g_M[bt * DD + jr], s0);
                atomicAdd(&g_M[bt * DD + jr + 8], s1);
            }
        }
    }
}

// ============================================================================
// Kernel 4: out[b][i] = (1/T) * sum_j g_M[b][j] * emb_w2[i][j] + emb_b2[i]
// ============================================================================
__global__ __launch_bounds__(128) void out_kernel(const float* __restrict__ w2,
                                                  const float* __restrict__ b2,
                                                  float* __restrict__ out)
{
    __shared__ float m[128];
    const int b = blockIdx.x;
    const int i = threadIdx.x;
    m[i] = g_M[b * DD + i] * (1.f / (float)TT);
    __syncthreads();
    float s = b2[i];
    const float* wr = w2 + i * DD;
#pragma unroll 16
    for (int j = 0; j < DD; j++) s = fmaf(m[j], wr[j], s);
    out[b * DD + i] = s;
}

// ----------------------------------------------------------------------------
extern "C" void kernel_launch(void* const* d_in, const int* in_sizes, int n_in,
                              void* d_out, int out_size)
{
    const float* x      = (const float*)d_in[0];
    const float* fc1_w  = (const float*)d_in[1];
    const float* fc1_b  = (const float*)d_in[2];
    const float* wih_f  = (const float*)d_in[3];
    const float* whh_f  = (const float*)d_in[4];
    const float* bih_f  = (const float*)d_in[5];
    const float* bhh_f  = (const float*)d_in[6];
    const float* wih_b  = (const float*)d_in[7];
    const float* whh_b  = (const float*)d_in[8];
    const float* bih_b  = (const float*)d_in[9];
    const float* bhh_b  = (const float*)d_in[10];
    const float* lout_w = (const float*)d_in[11];
    const float* lout_b = (const float*)d_in[12];
    const float* emb_w1 = (const float*)d_in[13];
    const float* emb_b1 = (const float*)d_in[14];
    const float* emb_w2 = (const float*)d_in[15];
    const float* emb_b2 = (const float*)d_in[16];
    float* out = (float*)d_out;

    cudaFuncSetAttribute(mega_kernel,
                         cudaFuncAttributeMaxDynamicSharedMemorySize, MEGA_B);

    prep_kernel<<<256, 256>>>(fc1_w, emb_w1);
    mega_kernel<<<dim3(TT / 128, BB), 256, MEGA_B>>>(
        x, fc1_b,
        wih_f, whh_f, bih_f, bhh_f,
        wih_b, whh_b, bih_b, bhh_b,
        lout_w, lout_b, emb_b1);
    out_kernel<<<BB, 128>>>(emb_w2, emb_b2, out);
}

// round 15
// speedup vs baseline: 2.7785x; 1.0302x over previous
#include <cuda_runtime.h>
#include <cstdint>

// Problem constants
#define BB   64
#define TT   512
#define NTOT 32768      // BB*TT
#define FF   1024
#define DD   128

// Scratch (device globals; no allocation allowed)
__device__ float g_M[BB * DD];          // sum over t of lrelu(e1)
__device__ unsigned g_wb[DD * (FF/2)];  // fc1_w bf16x2, layout [m][k2]
__device__ unsigned g_w1hi[DD * 64];    // emb_w1 hi bf16x2, layout [j][k2]
__device__ unsigned g_w1lo[DD * 64];    // emb_w1 lo residual bf16x2

// ---------------------------------------------------------------- helpers
__device__ __forceinline__ float mtanh(float x) {
    float y;
    asm("tanh.approx.f32 %0, %1;" : "=f"(y) : "f"(x));
    return y;
}
__device__ __forceinline__ unsigned sptr(const void* p) {
    return (unsigned)__cvta_generic_to_shared(p);
}
__device__ __forceinline__ void cp16(unsigned dst, const void* src) {
    asm volatile("cp.async.cg.shared.global [%0], [%1], 16;" :: "r"(dst), "l"(src));
}
#define CP_COMMIT() asm volatile("cp.async.commit_group;")
#define CP_WAIT0()  asm volatile("cp.async.wait_group 0;")

__device__ __forceinline__ unsigned pack_bf2(float kodd, float keven) {
    unsigned d;
    asm("cvt.rn.bf16x2.f32 %0, %1, %2;" : "=r"(d) : "f"(kodd), "f"(keven));
    return d;
}
__device__ __forceinline__ float bf_lo_val(unsigned p) { return __uint_as_float(p << 16); }
__device__ __forceinline__ float bf_hi_val(unsigned p) { return __uint_as_float(p & 0xffff0000u); }
__device__ __forceinline__ unsigned hadd2(unsigned a, unsigned b) {
    unsigned d;
    asm("add.rn.bf16x2 %0, %1, %2;" : "=r"(d) : "r"(a), "r"(b));
    return d;
}
__device__ __forceinline__ void ldsm_x4(unsigned r[4], unsigned addr) {
    asm volatile("ldmatrix.sync.aligned.m8n8.x4.shared.b16 {%0,%1,%2,%3}, [%4];"
                 : "=r"(r[0]), "=r"(r[1]), "=r"(r[2]), "=r"(r[3]) : "r"(addr));
}
__device__ __forceinline__ void mma_bf16(float c[4], const unsigned a[4], const unsigned b[2]) {
    asm volatile(
        "mma.sync.aligned.m16n8k16.row.col.f32.bf16.bf16.f32 "
        "{%0,%1,%2,%3}, {%4,%5,%6,%7}, {%8,%9}, {%0,%1,%2,%3};"
        : "+f"(c[0]), "+f"(c[1]), "+f"(c[2]), "+f"(c[3])
        : "r"(a[0]), "r"(a[1]), "r"(a[2]), "r"(a[3]), "r"(b[0]), "r"(b[1]));
}

// ============================================================================
// Kernel 0: prep — fc1_w -> g_wb [m][k2]; emb_w1 -> hi/lo split; zero g_M.
// ============================================================================
__global__ __launch_bounds__(256) void prep_kernel(const float* __restrict__ w,
                                                   const float* __restrict__ w1)
{
    const int idx = blockIdx.x * 256 + threadIdx.x;   // 0..65535
    {
        const int m  = idx >> 9;
        const int k2 = idx & 511;
        const float w0 = w[m * FF + 2 * k2];
        const float w1v = w[m * FF + 2 * k2 + 1];
        g_wb[m * 512 + k2] = pack_bf2(w1v, w0);
    }
    if (idx < DD * 64) {
        const int j  = idx >> 6;
        const int k2 = idx & 63;
        const float a0 = w1[j * DD + 2 * k2];
        const float a1 = w1[j * DD + 2 * k2 + 1];
        const unsigned hi = pack_bf2(a1, a0);
        const float l0 = a0 - bf_lo_val(hi);
        const float l1 = a1 - bf_hi_val(hi);
        g_w1hi[idx] = hi;
        g_w1lo[idx] = pack_bf2(l1, l0);
    }
    if (idx < BB * DD) g_M[idx] = 0.f;
}

// ============================================================================
// MEGAKERNEL: fc1 (bf16 HMMA) -> bi-LSTM -> emb1 (bf16 split HMMA), fused.
// CTA = one (batch bt, 128-wide t-tile). G lives ENTIRELY in smem as bf16
// n-pairs (overlapping the phase-1 ring, dead after the GEMM); the LSTM reads
// it via broadcast LDS; Y pairs go straight into the phase-3 B buffers.
// ============================================================================
#define P1A_U 2560                 // 128 rows x 20 (phase-1 A stage)
#define P1B_U 2176                 // 16 rows x 136 (phase-1 B stage)
#define RING_U (2*P1A_U + 2*P1B_U) // 9472 uints
#define SG_ST 65                   // G smem row stride (u32 pairs, padded)
#define P3A_U 1536                 // 128 rows x 12 (phase-3 A stage; reuses G region)
#define SY_ST 136
#define SY_U  (64 * SY_ST)         // 8704 uints per Y buffer
#define MEGA_U (RING_U + 2 * SY_U) // 26880 uints
#define MEGA_B (MEGA_U * 4)        // 107520 bytes

__global__ __launch_bounds__(256, 2) void mega_kernel(
    const float* __restrict__ x,    const float* __restrict__ fc1_b,
    const float* __restrict__ wih_f, const float* __restrict__ whh_f,
    const float* __restrict__ bih_f, const float* __restrict__ bhh_f,
    const float* __restrict__ wih_b, const float* __restrict__ whh_b,
    const float* __restrict__ bih_b, const float* __restrict__ bhh_b,
    const float* __restrict__ lout_w, const float* __restrict__ lout_b,
    const float* __restrict__ b1v)
{
    extern __shared__ __align__(16) unsigned smu[];
    unsigned* A_[2]; unsigned* B_[2];
    A_[0] = smu;             A_[1] = smu + P1A_U;
    B_[0] = smu + 2 * P1A_U; B_[1] = smu + 2 * P1A_U + P1B_U;
    unsigned* sG  = smu;                 // phase-1 epilogue .. phase-2 (8320 u)
    unsigned* sYf = smu + RING_U;
    unsigned* sYb = smu + RING_U + SY_U;

    const int tid  = threadIdx.x;
    const int lane = tid & 31;
    const int wid  = tid >> 5;
    const int g    = lane >> 2;
    const int tig  = lane & 3;
    const int wm   = (wid & 1) * 64;
    const int wn   = (wid >> 1) * 32;

    const int bt = blockIdx.y;
    const int t0 = blockIdx.x * 128;
    const float* xb = x + (size_t)bt * FF * TT;

    const int rowA  = tid >> 1;
    const int halfA = (tid & 1) * 8;
    const int kr = tid >> 4;
    const int q8 = (tid & 15) * 8;

    const unsigned lrow = wm + (lane & 7) + ((lane >> 3) & 1) * 8;
    const unsigned lak  = ((lane >> 4) & 1) * 4;

    float c[4][4][4];
#pragma unroll
    for (int i = 0; i < 4; i++)
#pragma unroll
        for (int j = 0; j < 4; j++)
#pragma unroll
            for (int k = 0; k < 4; k++) c[i][j][k] = 0.f;

    // ======================= Phase 1: fc1 GEMM =======================
    {
        const int NS = FF / 32;   // 32 stages

        // prologue: A(0)
        {
            const unsigned* srcA = g_wb + rowA * 512 + halfA;
            unsigned dst = sptr(A_[0] + rowA * 20 + halfA);
            cp16(dst, srcA); cp16(dst + 16, srcA + 4);
            CP_COMMIT();
        }
        float4 u0, u1, v0, v1;
        {
            const float* xp = xb + (size_t)(2 * kr) * TT + t0 + q8;
            u0 = *reinterpret_cast<const float4*>(xp);
            u1 = *reinterpret_cast<const float4*>(xp + 4);
            v0 = *reinterpret_cast<const float4*>(xp + TT);
            v1 = *reinterpret_cast<const float4*>(xp + TT + 4);
        }

        for (int s = 0; s < NS; s++) {
            // pack + store B(s)
            {
                unsigned* bp = B_[s & 1] + kr * 136 + q8;
                const float ue[8] = {u0.x, u0.y, u0.z, u0.w, u1.x, u1.y, u1.z, u1.w};
                const float vo[8] = {v0.x, v0.y, v0.z, v0.w, v1.x, v1.y, v1.z, v1.w};
                unsigned h[8];
#pragma unroll
                for (int i = 0; i < 8; i++) h[i] = pack_bf2(vo[i], ue[i]);
                *reinterpret_cast<uint4*>(bp)     = make_uint4(h[0], h[1], h[2], h[3]);
                *reinterpret_cast<uint4*>(bp + 4) = make_uint4(h[4], h[5], h[6], h[7]);
            }
            CP_WAIT0();          // A(s) landed
            __syncthreads();     // B(s) visible; buffer (s+1)&1 free

            if (s + 1 < NS) {
                const unsigned* srcA = g_wb + rowA * 512 + (s + 1) * 16 + halfA;
                unsigned dst = sptr(A_[(s + 1) & 1] + rowA * 20 + halfA);
                cp16(dst, srcA); cp16(dst + 16, srcA + 4);
            }
            CP_COMMIT();

            // prefetch B(s+1)
            {
                const int sn = (s + 1 < NS) ? s + 1 : s;
                const float* xp = xb + (size_t)(sn * 32 + 2 * kr) * TT + t0 + q8;
                u0 = *reinterpret_cast<const float4*>(xp);
                u1 = *reinterpret_cast<const float4*>(xp + 4);
                v0 = *reinterpret_cast<const float4*>(xp + TT);
                v1 = *reinterpret_cast<const float4*>(xp + TT + 4);
            }

            const unsigned Abase = sptr(A_[s & 1]);
            const unsigned* B = B_[s & 1];
#pragma unroll
            for (int g16 = 0; g16 < 2; g16++) {
                unsigned a[4][4], b[4][2];
#pragma unroll
                for (int mt = 0; mt < 4; mt++) {
                    const unsigned ad = Abase + ((lrow + mt * 16) * 20 + g16 * 8 + lak) * 4;
                    ldsm_x4(a[mt], ad);
                }
#pragma unroll
                for (int nt = 0; nt < 4; nt++) {
                    const int n = wn + nt * 8 + g;
                    b[nt][0] = B[(g16 * 8 + tig) * 136 + n];
                    b[nt][1] = B[(g16 * 8 + tig + 4) * 136 + n];
                }
#pragma unroll
                for (int mt = 0; mt < 4; mt++)
#pragma unroll
                    for (int nt = 0; nt < 4; nt++)
                        mma_bf16(c[mt][nt], a[mt], b[nt]);
            }
        }

        CP_WAIT0();
        __syncthreads();   // all MMAs done: ring region reusable as sG

        // epilogue: bias + pack to bf16 n-pairs in smem sG[d][n2]
#pragma unroll
        for (int mt = 0; mt < 4; mt++) {
            const int dr = wm + mt * 16 + g;
            const float bv0 = fc1_b[dr];
            const float bv1 = fc1_b[dr + 8];
#pragma unroll
            for (int nt = 0; nt < 4; nt++) {
                const int n2 = (wn + nt * 8) / 2 + tig;   // n-pair column
                sG[dr * SG_ST + n2] =
                    pack_bf2(c[mt][nt][1] + bv0, c[mt][nt][0] + bv0);
                sG[(dr + 8) * SG_ST + n2] =
                    pack_bf2(c[mt][nt][3] + bv1, c[mt][nt][2] + bv1);
            }
        }
    }
    __syncthreads();   // sG complete

    // ======================= Phase 2: bi-LSTM (smem-resident) ================
    {
        const int dir = tid >> 7;          // 0 fwd, 1 bwd
        const int nl  = tid & 127;

        const float* wih = dir ? wih_b : wih_f;
        const float* whh = dir ? whh_b : whh_f;
        const float* bih = dir ? bih_b : bih_f;
        const float* bhh = dir ? bhh_b : bhh_f;

        const float wi0 = 0.5f * wih[0], wh0 = 0.5f * whh[0], b0 = 0.5f * (bih[0] + bhh[0]);
        const float wi1 = 0.5f * wih[1], wh1 = 0.5f * whh[1], b1 = 0.5f * (bih[1] + bhh[1]);
        const float wi2 =        wih[2], wh2 =        whh[2], b2 =        (bih[2] + bhh[2]);
        const float wi3 = 0.5f * wih[3], wh3 = 0.5f * whh[3], b3 = 0.5f * (bih[3] + bhh[3]);

        const float lw = dir ? lout_w[1] : lout_w[0];
        const float lb = dir ? 0.f : lout_b[0];

        const int gst = dir ? -SG_ST : SG_ST;
        const unsigned* gp = sG + (dir ? 127 * SG_ST : 0) + (nl >> 1);
        const bool hi_half = (nl & 1);

        unsigned* yw = (dir ? (sYb + 63 * SY_ST) : sYf) + nl;
        const int yst = dir ? -SY_ST : SY_ST;

        float h = 0.f, cc = 0.f, yprev = 0.f;

#pragma unroll 8
        for (int it = 0; it < DD; it++) {
            const unsigned gw = *gp;
            gp += gst;
            const float xv = hi_half ? bf_hi_val(gw) : bf_lo_val(gw);

            const float ai = fmaf(wi0, xv, fmaf(wh0, h, b0));
            const float af = fmaf(wi1, xv, fmaf(wh1, h, b1));
            const float ag = fmaf(wi2, xv, fmaf(wh2, h, b2));
            const float ao = fmaf(wi3, xv, fmaf(wh3, h, b3));

            const float si = fmaf(0.5f, mtanh(ai), 0.5f);
            const float sf = fmaf(0.5f, mtanh(af), 0.5f);
            const float tg = mtanh(ag);
            const float so = fmaf(0.5f, mtanh(ao), 0.5f);

            cc = fmaf(sf, cc, si * tg);
            h = so * mtanh(cc);

            const float y = fmaf(lw, h, lb);
            if (it & 1) {
                *yw = dir ? pack_bf2(yprev, y) : pack_bf2(y, yprev);
                yw += yst;
            } else {
                yprev = y;
            }
        }
    }
    __syncthreads();   // sYf / sYb ready; sG dead

    // ======================= Phase 3: emb1 =======================
    {
        unsigned* AH_[2]; unsigned* AL_[2];
        AH_[0] = smu;             AH_[1] = smu + P3A_U;
        AL_[0] = smu + 2 * P3A_U; AL_[1] = smu + 3 * P3A_U;

        const int rowW  = tid >> 1;
        const int halfW = (tid & 1) * 4;

#pragma unroll
        for (int i = 0; i < 4; i++)
#pragma unroll
            for (int j = 0; j < 4; j++)
#pragma unroll
                for (int k = 0; k < 4; k++) c[i][j][k] = 0.f;

        // prologue: stage 0
        cp16(sptr(AH_[0] + rowW * 12 + halfW), g_w1hi + rowW * 64 + halfW);
        cp16(sptr(AL_[0] + rowW * 12 + halfW), g_w1lo + rowW * 64 + halfW);
        CP_COMMIT();

        for (int s = 0; s < 8; s++) {        // 8 stages of 8 k2-rows (k16 each)
            CP_WAIT0();          // A(s) landed
            __syncthreads();     // all warps past MMA(s-1): buffer (s+1)&1 free

            if (s + 1 < 8) {
                cp16(sptr(AH_[(s + 1) & 1] + rowW * 12 + halfW),
                     g_w1hi + rowW * 64 + (s + 1) * 8 + halfW);
                cp16(sptr(AL_[(s + 1) & 1] + rowW * 12 + halfW),
                     g_w1lo + rowW * 64 + (s + 1) * 8 + halfW);
            }
            CP_COMMIT();

            const unsigned AHb = sptr(AH_[s & 1]);
            const unsigned ALb = sptr(AL_[s & 1]);

            unsigned ah[4][4], al[4][4], b[4][2];
#pragma unroll
            for (int mt = 0; mt < 4; mt++) {
                const unsigned off = ((lrow + mt * 16) * 12 + lak) * 4;
                ldsm_x4(ah[mt], AHb + off);
                ldsm_x4(al[mt], ALb + off);
            }
#pragma unroll
            for (int nt = 0; nt < 4; nt++) {
                const int n = wn + nt * 8 + g;
                b[nt][0] = hadd2(sYf[(s * 8 + tig) * SY_ST + n],
                                 sYb[(s * 8 + tig) * SY_ST + n]);
                b[nt][1] = hadd2(sYf[(s * 8 + tig + 4) * SY_ST + n],
                                 sYb[(s * 8 + tig + 4) * SY_ST + n]);
            }
#pragma unroll
            for (int mt = 0; mt < 4; mt++)
#pragma unroll
                for (int nt = 0; nt < 4; nt++) {
                    mma_bf16(c[mt][nt], ah[mt], b[nt]);
                    mma_bf16(c[mt][nt], al[mt], b[nt]);
                }
        }

        // epilogue: bias + leaky-relu + sum over n, quad-reduce, atomicAdd
#pragma unroll
        for (int mt = 0; mt < 4; mt++) {
            const int jr = wm + mt * 16 + g;
            const float bv0 = b1v[jr];
            const float bv1 = b1v[jr + 8];
            float s0 = 0.f, s1 = 0.f;
#pragma unroll
            for (int nt = 0; nt < 4; nt++) {
                float e;
                e = c[mt][nt][0] + bv0; s0 += (e >= 0.f) ? e : 0.2f * e;
                e = c[mt][nt][1] + bv0; s0 += (e >= 0.f) ? e : 0.2f * e;
                e = c[mt][nt][2] + bv1; s1 += (e >= 0.f) ? e : 0.2f * e;
                e = c[mt][nt][3] + bv1; s1 += (e >= 0.f) ? e : 0.2f * e;
            }
            s0 += __shfl_xor_sync(0xffffffffu, s0, 1);
            s0 += __shfl_xor_sync(0xffffffffu, s0, 2);
            s1 += __shfl_xor_sync(0xffffffffu, s1, 1);
            s1 += __shfl_xor_sync(0xffffffffu, s1, 2);
            if (tig == 0) {
                atomicAdd(&g_M[bt * DD + jr], s0);
                atomicAdd(&g_M[bt * DD + jr + 8], s1);
            }
        }
    }
}

// ============================================================================
// Kernel 4: out[b][i] = (1/T) * sum_j g_M[b][j] * emb_w2[i][j] + emb_b2[i]
// ============================================================================
__global__ __launch_bounds__(128) void out_kernel(const float* __restrict__ w2,
                                                  const float* __restrict__ b2,
                                                  float* __restrict__ out)
{
    __shared__ float m[128];
    const int b = blockIdx.x;
    const int i = threadIdx.x;
    m[i] = g_M[b * DD + i] * (1.f / (float)TT);
    __syncthreads();
    float s = b2[i];
    const float* wr = w2 + i * DD;
#pragma unroll 16
    for (int j = 0; j < DD; j++) s = fmaf(m[j], wr[j], s);
    out[b * DD + i] = s;
}

// ----------------------------------------------------------------------------
extern "C" void kernel_launch(void* const* d_in, const int* in_sizes, int n_in,
                              void* d_out, int out_size)
{
    const float* x      = (const float*)d_in[0];
    const float* fc1_w  = (const float*)d_in[1];
    const float* fc1_b  = (const float*)d_in[2];
    const float* wih_f  = (const float*)d_in[3];
    const float* whh_f  = (const float*)d_in[4];
    const float* bih_f  = (const float*)d_in[5];
    const float* bhh_f  = (const float*)d_in[6];
    const float* wih_b  = (const float*)d_in[7];
    const float* whh_b  = (const float*)d_in[8];
    const float* bih_b  = (const float*)d_in[9];
    const float* bhh_b  = (const float*)d_in[10];
    const float* lout_w = (const float*)d_in[11];
    const float* lout_b = (const float*)d_in[12];
    const float* emb_w1 = (const float*)d_in[13];
    const float* emb_b1 = (const float*)d_in[14];
    const float* emb_w2 = (const float*)d_in[15];
    const float* emb_b2 = (const float*)d_in[16];
    float* out = (float*)d_out;

    cudaFuncSetAttribute(mega_kernel,
                         cudaFuncAttributeMaxDynamicSharedMemorySize, MEGA_B);

    prep_kernel<<<256, 256>>>(fc1_w, emb_w1);
    mega_kernel<<<dim3(TT / 128, BB), 256, MEGA_B>>>(
        x, fc1_b,
        wih_f, whh_f, bih_f, bhh_f,
        wih_b, whh_b, bih_b, bhh_b,
        lout_w, lout_b, emb_b1);
    out_kernel<<<BB, 128>>>(emb_w2, emb_b2, out);
}